// round 10
// baseline (speedup 1.0000x reference)
#include <cuda_runtime.h>
#include <cstdint>
#include <math.h>

#define D_MODEL 1024
#define NHEADS  16
#define DK      64
#define BATCH   4
#define SEQ     2048
#define MROWS   (BATCH * SEQ)   // 8192

// Scratch (allocation-free rule: __device__ globals)
__device__ float g_Q[MROWS * D_MODEL];
__device__ float g_K[MROWS * D_MODEL];
__device__ float g_V[MROWS * D_MODEL];
__device__ float g_H[MROWS * D_MODEL];
__device__ float g_Xt[MROWS * D_MODEL];
__device__ float g_Wqt[D_MODEL * D_MODEL];
__device__ float g_Wkt[D_MODEL * D_MODEL];
__device__ float g_Wvt[D_MODEL * D_MODEL];
__device__ float g_Wht[D_MODEL * D_MODEL];

__device__ __forceinline__ uint32_t f2tf(float f) {
    uint32_t r;
    asm("cvt.rna.tf32.f32 %0, %1;" : "=r"(r) : "f"(f));
    return r;
}
__device__ __forceinline__ float tfr(float f) { return __uint_as_float(f2tf(f)); }

__device__ __forceinline__ void mma_tf32(float* d, const uint32_t* a, const uint32_t* b) {
    asm volatile(
        "mma.sync.aligned.m16n8k8.row.col.f32.tf32.tf32.f32 "
        "{%0,%1,%2,%3}, {%4,%5,%6,%7}, {%8,%9}, {%0,%1,%2,%3};"
        : "+f"(d[0]), "+f"(d[1]), "+f"(d[2]), "+f"(d[3])
        : "r"(a[0]), "r"(a[1]), "r"(a[2]), "r"(a[3]), "r"(b[0]), "r"(b[1]));
}

__device__ __forceinline__ uint32_t smem_u32(const void* p) {
    uint32_t a;
    asm("{ .reg .u64 t; cvta.to.shared.u64 t, %1; cvt.u32.u64 %0, t; }" : "=r"(a) : "l"(p));
    return a;
}
__device__ __forceinline__ void cp16(uint32_t dst, const void* src) {
    asm volatile("cp.async.cg.shared.global [%0], [%1], 16;" :: "r"(dst), "l"(src) : "memory");
}
#define CP_COMMIT asm volatile("cp.async.commit_group;" ::: "memory")
#define CP_WAIT1  asm volatile("cp.async.wait_group 1;" ::: "memory")
#define CP_WAIT0  asm volatile("cp.async.wait_group 0;" ::: "memory")

// Fast 2^t on FMA/ALU pipes (no MUFU). |err| ~2.4e-6 rel. t clamped to [-126,100].
__device__ __forceinline__ float exp2p(float t) {
    t = fmaxf(fminf(t, 100.0f), -126.0f);
    const float MAGIC = 12582912.0f;
    float tm = t + MAGIC;
    float n  = tm - MAGIC;
    float f  = t - n;
    float p  = 1.3333558146428443e-3f;
    p = fmaf(p, f, 9.6181291976036003e-3f);
    p = fmaf(p, f, 5.5504108664821580e-2f);
    p = fmaf(p, f, 2.4022650695910071e-1f);
    p = fmaf(p, f, 6.9314718055994531e-1f);
    p = fmaf(p, f, 1.0f);
    int sc = (__float_as_int(tm) + (127 - 0x4B400000)) << 23;
    return p * __int_as_float(sc);
}
#define L2E 1.4426950408889634f

// 3-bit row permutation used as XOR swizzle key: conflict-free for K-style
// reads (row varies with lane>>2) AND V-style reads (row varies with lane&3).
__device__ __forceinline__ int perm3(int row) {
    return ((row & 3) << 1) | ((row >> 2) & 1);
}

// ---------------------------------------------------------------------------
// tf32 pre-rounding kernels
// ---------------------------------------------------------------------------
__global__ void cvt_tf32(float* __restrict__ dst, const float* __restrict__ src, int n4) {
    int i = blockIdx.x * blockDim.x + threadIdx.x;
    if (i < n4) {
        float4 v = ((const float4*)src)[i];
        ((uint4*)dst)[i] = make_uint4(f2tf(v.x), f2tf(v.y), f2tf(v.z), f2tf(v.w));
    }
}

__global__ void cvt_w4(float* d0, const float* s0, float* d1, const float* s1,
                       float* d2, const float* s2, float* d3, const float* s3, int n4) {
    int i = blockIdx.x * blockDim.x + threadIdx.x;
    const float* s; float* d;
    switch (blockIdx.y) {
        case 0:  s = s0; d = d0; break;
        case 1:  s = s1; d = d1; break;
        case 2:  s = s2; d = d2; break;
        default: s = s3; d = d3; break;
    }
    if (i < n4) {
        float4 v = ((const float4*)s)[i];
        ((uint4*)d)[i] = make_uint4(f2tf(v.x), f2tf(v.y), f2tf(v.z), f2tf(v.w));
    }
}

// ---------------------------------------------------------------------------
// TF32 GEMM core (NT), inputs pre-rounded tf32. BM=BN=128, BK=32, cp.async x2.
// (unchanged from round 6 baseline)
// ---------------------------------------------------------------------------
#define BM 128
#define BN 128
#define GNKT (D_MODEL / 32)   // 32

__device__ __forceinline__ void gemm_body(
    const float* __restrict__ A, const float* __restrict__ B,
    const float* __restrict__ bias, float* __restrict__ C,
    float scale, int outcvt, int m0, int n0, uint32_t* gsm)
{
    const uint32_t smemb = smem_u32(gsm);
    const int t = threadIdx.x, l = t & 31, w = t >> 5;
    const int wm = w & 1, wn = w >> 1;
    const int r = l >> 2, c = l & 3;

    uint32_t adst[4], bdst[4];
    const float *asrc[4], *bsrc[4];
#pragma unroll
    for (int i = 0; i < 4; i++) {
        const int ch = t + i * 256, rr = ch >> 3, g = ch & 7;
        const uint32_t d = (uint32_t)(rr * 32 + ((g ^ (rr & 7)) << 2)) * 4;
        adst[i] = d;
        bdst[i] = d + 16384;
        asrc[i] = A + (size_t)(m0 + rr) * D_MODEL + g * 4;
        bsrc[i] = B + (size_t)(n0 + rr) * D_MODEL + g * 4;
    }

    float acc[4][4][4];
#pragma unroll
    for (int mt = 0; mt < 4; mt++)
#pragma unroll
        for (int nt = 0; nt < 4; nt++)
#pragma unroll
            for (int q = 0; q < 4; q++) acc[mt][nt][q] = 0.f;

#pragma unroll
    for (int i = 0; i < 4; i++) { cp16(smemb + adst[i], asrc[i]); cp16(smemb + bdst[i], bsrc[i]); }
    CP_COMMIT;

    for (int kt = 0; kt < GNKT; kt++) {
        const int buf = kt & 1;
        if (kt + 1 < GNKT) {
            const int ko = (kt + 1) * 32;
            const uint32_t bo = (uint32_t)(buf ^ 1) * 32768u;
#pragma unroll
            for (int i = 0; i < 4; i++) {
                cp16(smemb + bo + adst[i], asrc[i] + ko);
                cp16(smemb + bo + bdst[i], bsrc[i] + ko);
            }
            CP_COMMIT;
            CP_WAIT1;
        } else {
            CP_WAIT0;
        }
        __syncthreads();

        const uint32_t* sa = gsm + buf * 8192;
        const uint32_t* sb = sa + 4096;
#pragma unroll
        for (int kk = 0; kk < 4; kk++) {
            const int g0 = 2 * kk, g1 = 2 * kk + 1;
            const int o0 = ((g0 ^ r) << 2) + c;
            const int o1 = ((g1 ^ r) << 2) + c;
            uint32_t af[4][4], bf[4][2];
#pragma unroll
            for (int mt = 0; mt < 4; mt++) {
                const int ra = (wm * 64 + mt * 16 + r) * 32;
                af[mt][0] = sa[ra + o0];
                af[mt][1] = sa[ra + 256 + o0];
                af[mt][2] = sa[ra + o1];
                af[mt][3] = sa[ra + 256 + o1];
            }
#pragma unroll
            for (int nt = 0; nt < 4; nt++) {
                const int rb = (wn * 32 + nt * 8 + r) * 32;
                bf[nt][0] = sb[rb + o0];
                bf[nt][1] = sb[rb + o1];
            }
#pragma unroll
            for (int mt = 0; mt < 4; mt++)
#pragma unroll
                for (int nt = 0; nt < 4; nt++)
                    mma_tf32(acc[mt][nt], af[mt], bf[nt]);
        }
        __syncthreads();
    }

    const int cc = c * 2;
#pragma unroll
    for (int mt = 0; mt < 4; mt++) {
        const int row0 = m0 + wm * 64 + mt * 16 + r;
#pragma unroll
        for (int nt = 0; nt < 4; nt++) {
            const int col = n0 + wn * 32 + nt * 8 + cc;
            float bx = 0.f, by = 0.f;
            if (bias) { bx = bias[col]; by = bias[col + 1]; }
            float v0 = acc[mt][nt][0] * scale + bx;
            float v1 = acc[mt][nt][1] * scale + by;
            float v2 = acc[mt][nt][2] * scale + bx;
            float v3 = acc[mt][nt][3] * scale + by;
            if (outcvt) { v0 = tfr(v0); v1 = tfr(v1); v2 = tfr(v2); v3 = tfr(v3); }
            *(float2*)(C + (size_t)row0 * D_MODEL + col) = make_float2(v0, v1);
            *(float2*)(C + (size_t)(row0 + 8) * D_MODEL + col) = make_float2(v2, v3);
        }
    }
}

// Fused QKV projection: blockIdx.x in [0,24): segment = bx>>3 selects W/C.
__global__ __launch_bounds__(256, 2) void gemm_qkv(
    const float* __restrict__ X,
    const float* __restrict__ Wq, const float* __restrict__ Wk, const float* __restrict__ Wv,
    float* __restrict__ Qo, float* __restrict__ Ko, float* __restrict__ Vo)
{
    extern __shared__ uint32_t gsm[];
    const int seg = blockIdx.x >> 3;
    const int n0  = (blockIdx.x & 7) * BN;
    const int m0  = blockIdx.y * BM;
    const float* B = (seg == 0) ? Wq : (seg == 1) ? Wk : Wv;
    float* C       = (seg == 0) ? Qo : (seg == 1) ? Ko : Vo;
    const float sc = (seg == 0) ? 0.125f : 1.0f;   // 1/sqrt(dk) folded into Q
    gemm_body(X, B, nullptr, C, sc, 1, m0, n0, gsm);
}

__global__ __launch_bounds__(256, 2) void gemm_out(
    const float* __restrict__ A, const float* __restrict__ B,
    const float* __restrict__ bias, float* __restrict__ C)
{
    extern __shared__ uint32_t gsm[];
    gemm_body(A, B, bias, C, 1.0f, 0, blockIdx.y * BM, blockIdx.x * BN, gsm);
}

// ---------------------------------------------------------------------------
// Tensor-core flash attention. BQ=512, 512 threads = 16 FAT warps x 32 q-rows.
// Q lives in SMEM (128KB); K AND V arrive via cp.async in [kv][d] layout with
// perm3 XOR swizzle (conflict-free for both K- and V-pattern fragment reads).
// Per-warp regs ~128 -> 4 warps/SMSP with full fat-warp K/V reuse.
// ---------------------------------------------------------------------------
#define FBQ 512
#define FTH 512
#define FNT (SEQ / 64)   // 32
// SMEM words: Q [0, 32768) ; K/V double buffer [32768, 49152)
#define FQW 32768
#define FSMB ((FQW + 16384) * 4)   // 196608 bytes

__global__ void __launch_bounds__(FTH, 1) flash_tc(
    const float* __restrict__ Q,
    const float* __restrict__ K,
    const float* __restrict__ V,
    float* __restrict__ O)
{
    extern __shared__ uint32_t fsm[];
    const uint32_t smemb = smem_u32(fsm);
    const int t = threadIdx.x, l = t & 31, w = t >> 5;   // w: 0..15
    const int r = l >> 2, c = l & 3;
    const int q0 = blockIdx.x * FBQ;
    const size_t base = (size_t)blockIdx.z * SEQ * D_MODEL + (size_t)blockIdx.y * DK;

    // K/V cp.async slots: 2 x 16B per array per thread (64 rows x 16 granules)
    uint32_t kdst[2], vdst[2];
    const float *ksrc[2], *vsrc[2];
#pragma unroll
    for (int i = 0; i < 2; i++) {
        const int idx = t + i * FTH, row = idx >> 4, gq = idx & 15;
        const int sg = (gq & 8) | ((gq ^ perm3(row)) & 7);
        kdst[i] = (uint32_t)(FQW + row * 64 + sg * 4) * 4;
        vdst[i] = kdst[i] + 4096 * 4;
        ksrc[i] = K + base + (size_t)row * D_MODEL + gq * 4;
        vsrc[i] = V + base + (size_t)row * D_MODEL + gq * 4;
    }

    // prologue: Q tile (512 rows) + K0/V0, one commit group
#pragma unroll
    for (int i = 0; i < 16; i++) {
        const int idx = t + i * FTH, row = idx >> 4, gq = idx & 15;
        const int sg = (gq & 8) | ((gq ^ perm3(row)) & 7);
        cp16(smemb + (uint32_t)(row * 64 + sg * 4) * 4,
             Q + base + (size_t)(q0 + row) * D_MODEL + gq * 4);
    }
#pragma unroll
    for (int i = 0; i < 2; i++) { cp16(smemb + kdst[i], ksrc[i]); cp16(smemb + vdst[i], vsrc[i]); }
    CP_COMMIT;

    float o[2][8][4];
#pragma unroll
    for (int mi = 0; mi < 2; mi++)
#pragma unroll
        for (int j = 0; j < 8; j++)
#pragma unroll
            for (int q = 0; q < 4; q++) o[mi][j][q] = 0.f;
    float lsA[2] = {0.f, 0.f};
    float lsB[2] = {0.f, 0.f};

    // Q fragment row slots: mi*2 + (reg&1) -> rows w*32 + {0,8,16,24} + r
    int qb[4], pr[4];
#pragma unroll
    for (int sl = 0; sl < 4; sl++) {
        const int row = w * 32 + sl * 8 + r;
        qb[sl] = row * 64 + c;
        pr[sl] = perm3(row);
    }
    const int pk = perm3(r);
    const int psrc = (l & ~3) | (c >> 1), psrc2 = psrc + 2;
    const bool podd = (c & 1);
    const int wv = r & 3, hv = r >> 2;
    const int key0 = c << 1, key1 = key0 | 1;

    for (int kt = 0; kt < FNT; kt++) {
        const int buf = kt & 1;
        if (kt + 1 < FNT) {
            const size_t go = (size_t)(kt + 1) * 64 * D_MODEL;
            const uint32_t bo = (uint32_t)(buf ^ 1) * (8192u * 4u);
#pragma unroll
            for (int i = 0; i < 2; i++) {
                cp16(smemb + bo + kdst[i], ksrc[i] + go);
                cp16(smemb + bo + vdst[i], vsrc[i] + go);
            }
            CP_COMMIT;
            CP_WAIT1;
        } else {
            CP_WAIT0;
        }
        __syncthreads();

        const uint32_t* sk = fsm + FQW + buf * 8192;
        const uint32_t* sv = sk + 4096;

#pragma unroll
        for (int half = 0; half < 2; half++) {
            // ---- S phase: kk outer (Q frag reused across 4 kv-chunks) ----
            float s[4][2][4];
#pragma unroll
            for (int nc = 0; nc < 4; nc++)
#pragma unroll
                for (int mi = 0; mi < 2; mi++)
#pragma unroll
                    for (int q = 0; q < 4; q++) s[nc][mi][q] = 0.f;

#pragma unroll
            for (int kk = 0; kk < 8; kk++) {
                const int gr0 = kk * 2, gr1 = gr0 + 1;
                const int e8 = gr0 & 8;
                uint32_t qa0[4], qa1[4];
                qa0[0] = fsm[qb[0] + (e8 | ((gr0 ^ pr[0]) & 7)) * 4];
                qa0[1] = fsm[qb[1] + (e8 | ((gr0 ^ pr[1]) & 7)) * 4];
                qa0[2] = fsm[qb[0] + (e8 | ((gr1 ^ pr[0]) & 7)) * 4];
                qa0[3] = fsm[qb[1] + (e8 | ((gr1 ^ pr[1]) & 7)) * 4];
                qa1[0] = fsm[qb[2] + (e8 | ((gr0 ^ pr[2]) & 7)) * 4];
                qa1[1] = fsm[qb[3] + (e8 | ((gr0 ^ pr[3]) & 7)) * 4];
                qa1[2] = fsm[qb[2] + (e8 | ((gr1 ^ pr[2]) & 7)) * 4];
                qa1[3] = fsm[qb[3] + (e8 | ((gr1 ^ pr[3]) & 7)) * 4];
                const int ok0 = (e8 | ((gr0 ^ pk) & 7)) * 4 + c;
                const int ok1 = (e8 | ((gr1 ^ pk) & 7)) * 4 + c;
#pragma unroll
                for (int nc = 0; nc < 4; nc++) {
                    const int krow = ((half * 4 + nc) * 8 + r) * 64;
                    uint32_t bf[2];
                    bf[0] = sk[krow + ok0];
                    bf[1] = sk[krow + ok1];
                    mma_tf32(s[nc][0], qa0, bf);
                    mma_tf32(s[nc][1], qa1, bf);
                }
            }

            // ---- exp + permute -> pac (reuses s registers) ----
            uint32_t pac[4][2][4];
#pragma unroll
            for (int nc = 0; nc < 4; nc++) {
#pragma unroll
                for (int mi = 0; mi < 2; mi++) {
                    const float e0 = exp2p(s[nc][mi][0] * L2E);
                    const float e1 = exp2p(s[nc][mi][1] * L2E);
                    const float e2 = exp2p(s[nc][mi][2] * L2E);
                    const float e3 = exp2p(s[nc][mi][3] * L2E);
                    lsA[mi] += e0 + e1;
                    lsB[mi] += e2 + e3;
                    const float x0 = __shfl_sync(0xffffffffu, e0, psrc);
                    const float x1 = __shfl_sync(0xffffffffu, e1, psrc);
                    const float y0 = __shfl_sync(0xffffffffu, e0, psrc2);
                    const float y1 = __shfl_sync(0xffffffffu, e1, psrc2);
                    const float z0 = __shfl_sync(0xffffffffu, e2, psrc);
                    const float z1 = __shfl_sync(0xffffffffu, e3, psrc);
                    const float w0 = __shfl_sync(0xffffffffu, e2, psrc2);
                    const float w1 = __shfl_sync(0xffffffffu, e3, psrc2);
                    pac[nc][mi][0] = f2tf(podd ? x1 : x0);
                    pac[nc][mi][1] = f2tf(podd ? z1 : z0);
                    pac[nc][mi][2] = f2tf(podd ? y1 : y0);
                    pac[nc][mi][3] = f2tf(podd ? w1 : w0);
                }
            }

            // ---- PV phase ----
#pragma unroll
            for (int nc = 0; nc < 4; nc++) {
                const int vrow0 = ((half * 4 + nc) * 8 + c) * 64;
                const int vrow1 = vrow0 + 4 * 64;
#pragma unroll
                for (int j = 0; j < 8; j++) {
                    const int grv = j * 2 + hv;
                    const int e8v = grv & 8;
                    uint32_t bf[2];
                    bf[0] = sv[vrow0 + (e8v | ((grv ^ key0) & 7)) * 4 + wv];
                    bf[1] = sv[vrow1 + (e8v | ((grv ^ key1) & 7)) * 4 + wv];
                    mma_tf32(o[0][j], pac[nc][0], bf);
                    mma_tf32(o[1][j], pac[nc][1], bf);
                }
            }
        }
        __syncthreads();
    }

    // ---- one-time l reduction, normalize + store (tf32-rounded) ----
#pragma unroll
    for (int mi = 0; mi < 2; mi++) {
#pragma unroll
        for (int off = 1; off <= 2; off <<= 1) {
            lsA[mi] += __shfl_xor_sync(0xffffffffu, lsA[mi], off);
            lsB[mi] += __shfl_xor_sync(0xffffffffu, lsB[mi], off);
        }
    }
#pragma unroll
    for (int mi = 0; mi < 2; mi++) {
        const float i0 = 1.0f / lsA[mi];
        const float i1 = 1.0f / lsB[mi];
        float* r0p = O + base + (size_t)(q0 + w * 32 + mi * 16 + r) * D_MODEL;
        float* r1p = r0p + 8 * D_MODEL;
#pragma unroll
        for (int j = 0; j < 8; j++) {
            const int col = j * 8 + c * 2;
            *(float2*)(r0p + col) = make_float2(tfr(o[mi][j][0] * i0), tfr(o[mi][j][1] * i0));
            *(float2*)(r1p + col) = make_float2(tfr(o[mi][j][2] * i1), tfr(o[mi][j][3] * i1));
        }
    }
}

// ---------------------------------------------------------------------------
extern "C" void kernel_launch(void* const* d_in, const int* in_sizes, int n_in,
                              void* d_out, int out_size)
{
    const float* X   = (const float*)d_in[0];
    const float* W_q = (const float*)d_in[1];
    const float* W_k = (const float*)d_in[2];
    const float* W_v = (const float*)d_in[3];
    const float* W_h = (const float*)d_in[4];
    const float* b_h = (const float*)d_in[5];
    float* out = (float*)d_out;

    float *Qp, *Kp, *Vp, *Hp, *Xt, *Wq, *Wk, *Wv, *Wh;
    cudaGetSymbolAddress((void**)&Qp, g_Q);
    cudaGetSymbolAddress((void**)&Kp, g_K);
    cudaGetSymbolAddress((void**)&Vp, g_V);
    cudaGetSymbolAddress((void**)&Hp, g_H);
    cudaGetSymbolAddress((void**)&Xt, g_Xt);
    cudaGetSymbolAddress((void**)&Wq, g_Wqt);
    cudaGetSymbolAddress((void**)&Wk, g_Wkt);
    cudaGetSymbolAddress((void**)&Wv, g_Wvt);
    cudaGetSymbolAddress((void**)&Wh, g_Wht);

    const int GSM = 65536;
    cudaFuncSetAttribute(gemm_qkv, cudaFuncAttributeMaxDynamicSharedMemorySize, GSM);
    cudaFuncSetAttribute(gemm_out, cudaFuncAttributeMaxDynamicSharedMemorySize, GSM);
    cudaFuncSetAttribute(flash_tc, cudaFuncAttributeMaxDynamicSharedMemorySize, FSMB);

    const int nX4 = MROWS * D_MODEL / 4;
    const int nW4 = D_MODEL * D_MODEL / 4;
    cvt_tf32<<<nX4 / 256, 256>>>(Xt, X, nX4);
    dim3 gw(nW4 / 256, 4);
    cvt_w4<<<gw, 256>>>(Wq, W_q, Wk, W_k, Wv, W_v, Wh, W_h, nW4);

    dim3 gq(24, MROWS / BM);             // fused QKV
    gemm_qkv<<<gq, 256, GSM>>>(Xt, Wq, Wk, Wv, Qp, Kp, Vp);

    dim3 gridF(SEQ / FBQ, NHEADS, BATCH);   // (4, 16, 4) = 256 CTAs
    flash_tc<<<gridF, FTH, FSMB>>>(Qp, Kp, Vp, Hp);

    dim3 gg(D_MODEL / BN, MROWS / BM);
    gemm_out<<<gg, 256, GSM>>>(Hp, Wh, b_h, out);
}

// round 11
// speedup vs baseline: 1.4025x; 1.4025x over previous
#include <cuda_runtime.h>
#include <cstdint>
#include <math.h>

#define D_MODEL 1024
#define NHEADS  16
#define DK      64
#define BATCH   4
#define SEQ     2048
#define MROWS   (BATCH * SEQ)   // 8192

// Scratch (allocation-free rule: __device__ globals)
__device__ float g_Q[MROWS * D_MODEL];
__device__ float g_K[MROWS * D_MODEL];
__device__ float g_V[MROWS * D_MODEL];
__device__ float g_H[MROWS * D_MODEL];
__device__ float g_Xt[MROWS * D_MODEL];
__device__ float g_Wqt[D_MODEL * D_MODEL];
__device__ float g_Wkt[D_MODEL * D_MODEL];
__device__ float g_Wvt[D_MODEL * D_MODEL];
__device__ float g_Wht[D_MODEL * D_MODEL];

__device__ __forceinline__ uint32_t f2tf(float f) {
    uint32_t r;
    asm("cvt.rna.tf32.f32 %0, %1;" : "=r"(r) : "f"(f));
    return r;
}
__device__ __forceinline__ float tfr(float f) { return __uint_as_float(f2tf(f)); }

__device__ __forceinline__ void mma_tf32(float* d, const uint32_t* a, const uint32_t* b) {
    asm volatile(
        "mma.sync.aligned.m16n8k8.row.col.f32.tf32.tf32.f32 "
        "{%0,%1,%2,%3}, {%4,%5,%6,%7}, {%8,%9}, {%0,%1,%2,%3};"
        : "+f"(d[0]), "+f"(d[1]), "+f"(d[2]), "+f"(d[3])
        : "r"(a[0]), "r"(a[1]), "r"(a[2]), "r"(a[3]), "r"(b[0]), "r"(b[1]));
}

__device__ __forceinline__ uint32_t smem_u32(const void* p) {
    uint32_t a;
    asm("{ .reg .u64 t; cvta.to.shared.u64 t, %1; cvt.u32.u64 %0, t; }" : "=r"(a) : "l"(p));
    return a;
}
__device__ __forceinline__ void cp16(uint32_t dst, const void* src) {
    asm volatile("cp.async.cg.shared.global [%0], [%1], 16;" :: "r"(dst), "l"(src) : "memory");
}
#define CP_COMMIT asm volatile("cp.async.commit_group;" ::: "memory")
#define CP_WAIT1  asm volatile("cp.async.wait_group 1;" ::: "memory")
#define CP_WAIT0  asm volatile("cp.async.wait_group 0;" ::: "memory")

// Fast 2^t on FMA/ALU pipes (no MUFU). |err| ~2.4e-6 rel. t clamped to [-126,100].
__device__ __forceinline__ float exp2p(float t) {
    t = fmaxf(fminf(t, 100.0f), -126.0f);
    const float MAGIC = 12582912.0f;
    float tm = t + MAGIC;
    float n  = tm - MAGIC;
    float f  = t - n;
    float p  = 1.3333558146428443e-3f;
    p = fmaf(p, f, 9.6181291976036003e-3f);
    p = fmaf(p, f, 5.5504108664821580e-2f);
    p = fmaf(p, f, 2.4022650695910071e-1f);
    p = fmaf(p, f, 6.9314718055994531e-1f);
    p = fmaf(p, f, 1.0f);
    int sc = (__float_as_int(tm) + (127 - 0x4B400000)) << 23;
    return p * __int_as_float(sc);
}
#define L2E 1.4426950408889634f

// 3-bit row permutation as XOR swizzle key: conflict-free for K-pattern reads
// (lane spread on r=l>>2) AND V-pattern reads (lane spread on c=l&3).
__device__ __forceinline__ int perm3(int row) {
    return ((row & 3) << 1) | ((row >> 2) & 1);
}

// ---------------------------------------------------------------------------
// tf32 pre-rounding kernels
// ---------------------------------------------------------------------------
__global__ void cvt_tf32(float* __restrict__ dst, const float* __restrict__ src, int n4) {
    int i = blockIdx.x * blockDim.x + threadIdx.x;
    if (i < n4) {
        float4 v = ((const float4*)src)[i];
        ((uint4*)dst)[i] = make_uint4(f2tf(v.x), f2tf(v.y), f2tf(v.z), f2tf(v.w));
    }
}

__global__ void cvt_w4(float* d0, const float* s0, float* d1, const float* s1,
                       float* d2, const float* s2, float* d3, const float* s3, int n4) {
    int i = blockIdx.x * blockDim.x + threadIdx.x;
    const float* s; float* d;
    switch (blockIdx.y) {
        case 0:  s = s0; d = d0; break;
        case 1:  s = s1; d = d1; break;
        case 2:  s = s2; d = d2; break;
        default: s = s3; d = d3; break;
    }
    if (i < n4) {
        float4 v = ((const float4*)s)[i];
        ((uint4*)d)[i] = make_uint4(f2tf(v.x), f2tf(v.y), f2tf(v.z), f2tf(v.w));
    }
}

// ---------------------------------------------------------------------------
// TF32 GEMM core (NT), inputs pre-rounded tf32. BM=BN=128, BK=32, cp.async x2.
// (unchanged from round 6)
// ---------------------------------------------------------------------------
#define BM 128
#define BN 128
#define GNKT (D_MODEL / 32)   // 32

__device__ __forceinline__ void gemm_body(
    const float* __restrict__ A, const float* __restrict__ B,
    const float* __restrict__ bias, float* __restrict__ C,
    float scale, int outcvt, int m0, int n0, uint32_t* gsm)
{
    const uint32_t smemb = smem_u32(gsm);
    const int t = threadIdx.x, l = t & 31, w = t >> 5;
    const int wm = w & 1, wn = w >> 1;
    const int r = l >> 2, c = l & 3;

    uint32_t adst[4], bdst[4];
    const float *asrc[4], *bsrc[4];
#pragma unroll
    for (int i = 0; i < 4; i++) {
        const int ch = t + i * 256, rr = ch >> 3, g = ch & 7;
        const uint32_t d = (uint32_t)(rr * 32 + ((g ^ (rr & 7)) << 2)) * 4;
        adst[i] = d;
        bdst[i] = d + 16384;
        asrc[i] = A + (size_t)(m0 + rr) * D_MODEL + g * 4;
        bsrc[i] = B + (size_t)(n0 + rr) * D_MODEL + g * 4;
    }

    float acc[4][4][4];
#pragma unroll
    for (int mt = 0; mt < 4; mt++)
#pragma unroll
        for (int nt = 0; nt < 4; nt++)
#pragma unroll
            for (int q = 0; q < 4; q++) acc[mt][nt][q] = 0.f;

#pragma unroll
    for (int i = 0; i < 4; i++) { cp16(smemb + adst[i], asrc[i]); cp16(smemb + bdst[i], bsrc[i]); }
    CP_COMMIT;

    for (int kt = 0; kt < GNKT; kt++) {
        const int buf = kt & 1;
        if (kt + 1 < GNKT) {
            const int ko = (kt + 1) * 32;
            const uint32_t bo = (uint32_t)(buf ^ 1) * 32768u;
#pragma unroll
            for (int i = 0; i < 4; i++) {
                cp16(smemb + bo + adst[i], asrc[i] + ko);
                cp16(smemb + bo + bdst[i], bsrc[i] + ko);
            }
            CP_COMMIT;
            CP_WAIT1;
        } else {
            CP_WAIT0;
        }
        __syncthreads();

        const uint32_t* sa = gsm + buf * 8192;
        const uint32_t* sb = sa + 4096;
#pragma unroll
        for (int kk = 0; kk < 4; kk++) {
            const int g0 = 2 * kk, g1 = 2 * kk + 1;
            const int o0 = ((g0 ^ r) << 2) + c;
            const int o1 = ((g1 ^ r) << 2) + c;
            uint32_t af[4][4], bf[4][2];
#pragma unroll
            for (int mt = 0; mt < 4; mt++) {
                const int ra = (wm * 64 + mt * 16 + r) * 32;
                af[mt][0] = sa[ra + o0];
                af[mt][1] = sa[ra + 256 + o0];
                af[mt][2] = sa[ra + o1];
                af[mt][3] = sa[ra + 256 + o1];
            }
#pragma unroll
            for (int nt = 0; nt < 4; nt++) {
                const int rb = (wn * 32 + nt * 8 + r) * 32;
                bf[nt][0] = sb[rb + o0];
                bf[nt][1] = sb[rb + o1];
            }
#pragma unroll
            for (int mt = 0; mt < 4; mt++)
#pragma unroll
                for (int nt = 0; nt < 4; nt++)
                    mma_tf32(acc[mt][nt], af[mt], bf[nt]);
        }
        __syncthreads();
    }

    const int cc = c * 2;
#pragma unroll
    for (int mt = 0; mt < 4; mt++) {
        const int row0 = m0 + wm * 64 + mt * 16 + r;
#pragma unroll
        for (int nt = 0; nt < 4; nt++) {
            const int col = n0 + wn * 32 + nt * 8 + cc;
            float bx = 0.f, by = 0.f;
            if (bias) { bx = bias[col]; by = bias[col + 1]; }
            float v0 = acc[mt][nt][0] * scale + bx;
            float v1 = acc[mt][nt][1] * scale + by;
            float v2 = acc[mt][nt][2] * scale + bx;
            float v3 = acc[mt][nt][3] * scale + by;
            if (outcvt) { v0 = tfr(v0); v1 = tfr(v1); v2 = tfr(v2); v3 = tfr(v3); }
            *(float2*)(C + (size_t)row0 * D_MODEL + col) = make_float2(v0, v1);
            *(float2*)(C + (size_t)(row0 + 8) * D_MODEL + col) = make_float2(v2, v3);
        }
    }
}

// Fused QKV projection: blockIdx.x in [0,24): segment = bx>>3 selects W/C.
__global__ __launch_bounds__(256, 2) void gemm_qkv(
    const float* __restrict__ X,
    const float* __restrict__ Wq, const float* __restrict__ Wk, const float* __restrict__ Wv,
    float* __restrict__ Qo, float* __restrict__ Ko, float* __restrict__ Vo)
{
    extern __shared__ uint32_t gsm[];
    const int seg = blockIdx.x >> 3;
    const int n0  = (blockIdx.x & 7) * BN;
    const int m0  = blockIdx.y * BM;
    const float* B = (seg == 0) ? Wq : (seg == 1) ? Wk : Wv;
    float* C       = (seg == 0) ? Qo : (seg == 1) ? Ko : Vo;
    const float sc = (seg == 0) ? 0.125f : 1.0f;   // 1/sqrt(dk) folded into Q
    gemm_body(X, B, nullptr, C, sc, 1, m0, n0, gsm);
}

__global__ __launch_bounds__(256, 2) void gemm_out(
    const float* __restrict__ A, const float* __restrict__ B,
    const float* __restrict__ bias, float* __restrict__ C)
{
    extern __shared__ uint32_t gsm[];
    gemm_body(A, B, bias, C, 1.0f, 0, blockIdx.y * BM, blockIdx.x * BN, gsm);
}

// ---------------------------------------------------------------------------
// Tensor-core flash attention. 128 threads = 4 FAT warps x 32 q-rows, BQ=128.
// Small CTA -> 2 CTAs/SM (4 warps/SMSP) with the fat-warp register budget.
// K and V both cp.async into [kv][d] layout with perm3 XOR swizzle
// (conflict-free for both K-pattern and V-pattern fragment reads).
// ---------------------------------------------------------------------------
#define FBQ 128
#define FTH 128
#define FNT (SEQ / 64)   // 32

__global__ void __launch_bounds__(FTH, 2) flash_tc(
    const float* __restrict__ Q,
    const float* __restrict__ K,
    const float* __restrict__ V,
    float* __restrict__ O)
{
    extern __shared__ uint32_t fsm[];   // [2][ K 4096 | V 4096 ] words = 64KB
    const uint32_t smemb = smem_u32(fsm);
    const int t = threadIdx.x, l = t & 31, w = t >> 5;   // w: 0..3
    const int r = l >> 2, c = l & 3;
    const int q0 = blockIdx.x * FBQ;
    const size_t base = (size_t)blockIdx.z * SEQ * D_MODEL + (size_t)blockIdx.y * DK;

    // Q A-fragments: 32 q-rows per warp (pre-rounded tf32, scale folded)
    uint32_t qa[2][8][4];
#pragma unroll
    for (int mi = 0; mi < 2; mi++) {
        const float* qp0 = Q + base + (size_t)(q0 + w * 32 + mi * 16 + r) * D_MODEL;
        const float* qp1 = qp0 + 8 * D_MODEL;
#pragma unroll
        for (int kk = 0; kk < 8; kk++) {
            qa[mi][kk][0] = __float_as_uint(qp0[kk * 8 + c]);
            qa[mi][kk][1] = __float_as_uint(qp1[kk * 8 + c]);
            qa[mi][kk][2] = __float_as_uint(qp0[kk * 8 + c + 4]);
            qa[mi][kk][3] = __float_as_uint(qp1[kk * 8 + c + 4]);
        }
    }

    float o[2][8][4];
#pragma unroll
    for (int mi = 0; mi < 2; mi++)
#pragma unroll
        for (int j = 0; j < 8; j++)
#pragma unroll
            for (int q = 0; q < 4; q++) o[mi][j][q] = 0.f;
    float lsA[2] = {0.f, 0.f};
    float lsB[2] = {0.f, 0.f};

    // K/V loader: thread covers rows r0+8i (i=0..7), granule gq. The swizzled
    // granule sg is invariant across i (perm3 depends only on row&3 and
    // (row>>2)&1, both constant under +8).
    const int gq = t & 15;
    const int r0 = t >> 4;   // 0..7
    const int sgk = (gq & 8) | ((gq ^ perm3(r0)) & 7);
    const uint32_t kd0 = (uint32_t)(r0 * 64 + sgk * 4) * 4;   // bytes
    const float* kbase = K + base + (size_t)r0 * D_MODEL + gq * 4;
    const float* vbase = V + base + (size_t)r0 * D_MODEL + gq * 4;

    // preload kt = 0
#pragma unroll
    for (int i = 0; i < 8; i++) {
        cp16(smemb + kd0 + i * 2048u, kbase + (size_t)i * 8 * D_MODEL);
        cp16(smemb + 16384u + kd0 + i * 2048u, vbase + (size_t)i * 8 * D_MODEL);
    }
    CP_COMMIT;

    const int pk = perm3(r);
    const int psrc = (l & ~3) | (c >> 1), psrc2 = psrc + 2;
    const bool podd = (c & 1);
    const int relem = r & 3;      // PV: element within d-granule
    const int gadd  = r >> 2;     // PV: g = 2j + gadd
    const int key0 = c << 1, key1 = key0 | 1;

    for (int kt = 0; kt < FNT; kt++) {
        const int buf = kt & 1;
        if (kt + 1 < FNT) {
            const size_t go = (size_t)(kt + 1) * 64 * D_MODEL;
            const uint32_t bo = (uint32_t)(buf ^ 1) * 32768u;
#pragma unroll
            for (int i = 0; i < 8; i++) {
                cp16(smemb + bo + kd0 + i * 2048u, kbase + go + (size_t)i * 8 * D_MODEL);
                cp16(smemb + bo + 16384u + kd0 + i * 2048u, vbase + go + (size_t)i * 8 * D_MODEL);
            }
            CP_COMMIT;
            CP_WAIT1;
        } else {
            CP_WAIT0;
        }
        __syncthreads();

        const uint32_t* sk = fsm + buf * 8192;
        const uint32_t* sv = sk + 4096;

        // ---- S = Q K^T (full 128x64 per warp-pair layout) ----
        float s[2][8][4];
#pragma unroll
        for (int mi = 0; mi < 2; mi++)
#pragma unroll
            for (int j = 0; j < 8; j++)
#pragma unroll
                for (int q = 0; q < 4; q++) s[mi][j][q] = 0.f;

#pragma unroll
        for (int kk = 0; kk < 8; kk++) {
            const int g0 = 2 * kk, g1 = 2 * kk + 1;
            const int ok0 = ((g0 & 8) | ((g0 ^ pk) & 7)) * 4 + c;
            const int ok1 = ((g1 & 8) | ((g1 ^ pk) & 7)) * 4 + c;
#pragma unroll
            for (int j = 0; j < 8; j++) {
                const int row = (j * 8 + r) * 64;
                uint32_t bf[2];
                bf[0] = sk[row + ok0];
                bf[1] = sk[row + ok1];
                mma_tf32(s[0][j], qa[0][kk], bf);
                mma_tf32(s[1][j], qa[1][kk], bf);
            }
        }

        // ---- per kv-chunk kk: exp + permute + PV ----
#pragma unroll
        for (int kk = 0; kk < 8; kk++) {
            uint32_t pac[2][4];
#pragma unroll
            for (int mi = 0; mi < 2; mi++) {
                const float e0 = exp2p(s[mi][kk][0] * L2E);
                const float e1 = exp2p(s[mi][kk][1] * L2E);
                const float e2 = exp2p(s[mi][kk][2] * L2E);
                const float e3 = exp2p(s[mi][kk][3] * L2E);
                lsA[mi] += e0 + e1;
                lsB[mi] += e2 + e3;
                const float x0 = __shfl_sync(0xffffffffu, e0, psrc);
                const float x1 = __shfl_sync(0xffffffffu, e1, psrc);
                const float y0 = __shfl_sync(0xffffffffu, e0, psrc2);
                const float y1 = __shfl_sync(0xffffffffu, e1, psrc2);
                const float z0 = __shfl_sync(0xffffffffu, e2, psrc);
                const float z1 = __shfl_sync(0xffffffffu, e3, psrc);
                const float w0 = __shfl_sync(0xffffffffu, e2, psrc2);
                const float w1 = __shfl_sync(0xffffffffu, e3, psrc2);
                pac[mi][0] = f2tf(podd ? x1 : x0);
                pac[mi][1] = f2tf(podd ? z1 : z0);
                pac[mi][2] = f2tf(podd ? y1 : y0);
                pac[mi][3] = f2tf(podd ? w1 : w0);
            }

            // O += P[:, kk-chunk] x V[kk-chunk, :]  (V in [kv][d], perm3 swizzle)
            const int rowA = (kk * 8 + c) * 64;        // kv = kk*8 + c
            const int rowB = rowA + 4 * 64;            // kv = kk*8 + c + 4
#pragma unroll
            for (int j = 0; j < 8; j++) {
                const int g = 2 * j + gadd;
                const int e8 = g & 8;
                uint32_t bf[2];
                bf[0] = sv[rowA + (e8 | ((g ^ key0) & 7)) * 4 + relem];
                bf[1] = sv[rowB + (e8 | ((g ^ key1) & 7)) * 4 + relem];
                mma_tf32(o[0][j], pac[0], bf);
                mma_tf32(o[1][j], pac[1], bf);
            }
        }
        __syncthreads();
    }

    // ---- one-time l reduction, normalize + store (tf32-rounded) ----
#pragma unroll
    for (int mi = 0; mi < 2; mi++) {
#pragma unroll
        for (int off = 1; off <= 2; off <<= 1) {
            lsA[mi] += __shfl_xor_sync(0xffffffffu, lsA[mi], off);
            lsB[mi] += __shfl_xor_sync(0xffffffffu, lsB[mi], off);
        }
    }
#pragma unroll
    for (int mi = 0; mi < 2; mi++) {
        const float i0 = 1.0f / lsA[mi];
        const float i1 = 1.0f / lsB[mi];
        float* r0p = O + base + (size_t)(q0 + w * 32 + mi * 16 + r) * D_MODEL;
        float* r1p = r0p + 8 * D_MODEL;
#pragma unroll
        for (int j = 0; j < 8; j++) {
            const int col = j * 8 + c * 2;
            *(float2*)(r0p + col) = make_float2(tfr(o[mi][j][0] * i0), tfr(o[mi][j][1] * i0));
            *(float2*)(r1p + col) = make_float2(tfr(o[mi][j][2] * i1), tfr(o[mi][j][3] * i1));
        }
    }
}

// ---------------------------------------------------------------------------
extern "C" void kernel_launch(void* const* d_in, const int* in_sizes, int n_in,
                              void* d_out, int out_size)
{
    const float* X   = (const float*)d_in[0];
    const float* W_q = (const float*)d_in[1];
    const float* W_k = (const float*)d_in[2];
    const float* W_v = (const float*)d_in[3];
    const float* W_h = (const float*)d_in[4];
    const float* b_h = (const float*)d_in[5];
    float* out = (float*)d_out;

    float *Qp, *Kp, *Vp, *Hp, *Xt, *Wq, *Wk, *Wv, *Wh;
    cudaGetSymbolAddress((void**)&Qp, g_Q);
    cudaGetSymbolAddress((void**)&Kp, g_K);
    cudaGetSymbolAddress((void**)&Vp, g_V);
    cudaGetSymbolAddress((void**)&Hp, g_H);
    cudaGetSymbolAddress((void**)&Xt, g_Xt);
    cudaGetSymbolAddress((void**)&Wq, g_Wqt);
    cudaGetSymbolAddress((void**)&Wk, g_Wkt);
    cudaGetSymbolAddress((void**)&Wv, g_Wvt);
    cudaGetSymbolAddress((void**)&Wh, g_Wht);

    const int GSM = 65536, FSM = 65536;
    cudaFuncSetAttribute(gemm_qkv, cudaFuncAttributeMaxDynamicSharedMemorySize, GSM);
    cudaFuncSetAttribute(gemm_out, cudaFuncAttributeMaxDynamicSharedMemorySize, GSM);
    cudaFuncSetAttribute(flash_tc, cudaFuncAttributeMaxDynamicSharedMemorySize, FSM);

    const int nX4 = MROWS * D_MODEL / 4;
    const int nW4 = D_MODEL * D_MODEL / 4;
    cvt_tf32<<<nX4 / 256, 256>>>(Xt, X, nX4);
    dim3 gw(nW4 / 256, 4);
    cvt_w4<<<gw, 256>>>(Wq, W_q, Wk, W_k, Wv, W_v, Wh, W_h, nW4);

    dim3 gq(24, MROWS / BM);             // fused QKV
    gemm_qkv<<<gq, 256, GSM>>>(Xt, Wq, Wk, Wv, Qp, Kp, Vp);

    dim3 gridF(SEQ / FBQ, NHEADS, BATCH);   // (16, 16, 4) = 1024 CTAs
    flash_tc<<<gridF, FTH, FSM>>>(Qp, Kp, Vp, Hp);

    dim3 gg(D_MODEL / BN, MROWS / BM);
    gemm_out<<<gg, 256, GSM>>>(Hp, Wh, b_h, out);
}

// round 12
// speedup vs baseline: 1.6949x; 1.2085x over previous
#include <cuda_runtime.h>
#include <cuda_fp16.h>
#include <cstdint>
#include <math.h>

#define D_MODEL 1024
#define NHEADS  16
#define DK      64
#define BATCH   4
#define SEQ     2048
#define MROWS   (BATCH * SEQ)   // 8192

// Scratch (allocation-free rule: __device__ globals)
__device__ float g_Q[MROWS * D_MODEL];
__device__ float g_K[MROWS * D_MODEL];
__device__ float g_V[MROWS * D_MODEL];
__device__ float g_H[MROWS * D_MODEL];
__device__ float g_Xt[MROWS * D_MODEL];
__device__ float g_Wqt[D_MODEL * D_MODEL];
__device__ float g_Wkt[D_MODEL * D_MODEL];
__device__ float g_Wvt[D_MODEL * D_MODEL];
__device__ float g_Wht[D_MODEL * D_MODEL];
__device__ __half g_VtT[BATCH * NHEADS * DK * SEQ];   // V transposed fp16 [bh][d][kv]

__device__ __forceinline__ uint32_t f2tf(float f) {
    uint32_t r;
    asm("cvt.rna.tf32.f32 %0, %1;" : "=r"(r) : "f"(f));
    return r;
}
__device__ __forceinline__ float tfr(float f) { return __uint_as_float(f2tf(f)); }

__device__ __forceinline__ void mma_tf32(float* d, const uint32_t* a, const uint32_t* b) {
    asm volatile(
        "mma.sync.aligned.m16n8k8.row.col.f32.tf32.tf32.f32 "
        "{%0,%1,%2,%3}, {%4,%5,%6,%7}, {%8,%9}, {%0,%1,%2,%3};"
        : "+f"(d[0]), "+f"(d[1]), "+f"(d[2]), "+f"(d[3])
        : "r"(a[0]), "r"(a[1]), "r"(a[2]), "r"(a[3]), "r"(b[0]), "r"(b[1]));
}

// fp16 PV MMA: D(f32) += A(f16) * B(f16), m16n8k16
__device__ __forceinline__ void mma_f16(float* d, const uint32_t* a, uint32_t b0, uint32_t b1) {
    asm volatile(
        "mma.sync.aligned.m16n8k16.row.col.f32.f16.f16.f32 "
        "{%0,%1,%2,%3}, {%4,%5,%6,%7}, {%8,%9}, {%0,%1,%2,%3};"
        : "+f"(d[0]), "+f"(d[1]), "+f"(d[2]), "+f"(d[3])
        : "r"(a[0]), "r"(a[1]), "r"(a[2]), "r"(a[3]), "r"(b0), "r"(b1));
}

__device__ __forceinline__ uint32_t h2pack(float lo, float hi) {
    uint32_t r;
    asm("cvt.rn.f16x2.f32 %0, %1, %2;" : "=r"(r) : "f"(hi), "f"(lo));
    return r;
}

__device__ __forceinline__ uint32_t smem_u32(const void* p) {
    uint32_t a;
    asm("{ .reg .u64 t; cvta.to.shared.u64 t, %1; cvt.u32.u64 %0, t; }" : "=r"(a) : "l"(p));
    return a;
}
__device__ __forceinline__ void cp16(uint32_t dst, const void* src) {
    asm volatile("cp.async.cg.shared.global [%0], [%1], 16;" :: "r"(dst), "l"(src) : "memory");
}
#define CP_COMMIT asm volatile("cp.async.commit_group;" ::: "memory")
#define CP_WAIT1  asm volatile("cp.async.wait_group 1;" ::: "memory")
#define CP_WAIT0  asm volatile("cp.async.wait_group 0;" ::: "memory")

// Fast 2^t on FMA/ALU pipes (no MUFU). |err| ~2.4e-6 rel.
__device__ __forceinline__ float exp2p(float t) {
    t = fmaxf(t, -126.0f);
    const float MAGIC = 12582912.0f;
    float tm = t + MAGIC;
    float n  = tm - MAGIC;
    float f  = t - n;
    float p  = 1.3333558146428443e-3f;
    p = fmaf(p, f, 9.6181291976036003e-3f);
    p = fmaf(p, f, 5.5504108664821580e-2f);
    p = fmaf(p, f, 2.4022650695910071e-1f);
    p = fmaf(p, f, 6.9314718055994531e-1f);
    p = fmaf(p, f, 1.0f);
    int sc = (__float_as_int(tm) + (127 - 0x4B400000)) << 23;
    return p * __int_as_float(sc);
}
#define L2E 1.4426950408889634f
// exp for fp16-bound P: clamp exponent so e^s < 61k (fp16 max 65504)
__device__ __forceinline__ float expc(float s) { return exp2p(fminf(s * L2E, 15.9f)); }

// 3-bit row permutation as XOR swizzle key (K path, round-11 proven)
__device__ __forceinline__ int perm3(int row) {
    return ((row & 3) << 1) | ((row >> 2) & 1);
}

// ---------------------------------------------------------------------------
// tf32 pre-rounding kernels
// ---------------------------------------------------------------------------
__global__ void cvt_tf32(float* __restrict__ dst, const float* __restrict__ src, int n4) {
    int i = blockIdx.x * blockDim.x + threadIdx.x;
    if (i < n4) {
        float4 v = ((const float4*)src)[i];
        ((uint4*)dst)[i] = make_uint4(f2tf(v.x), f2tf(v.y), f2tf(v.z), f2tf(v.w));
    }
}

__global__ void cvt_w4(float* d0, const float* s0, float* d1, const float* s1,
                       float* d2, const float* s2, float* d3, const float* s3, int n4) {
    int i = blockIdx.x * blockDim.x + threadIdx.x;
    const float* s; float* d;
    switch (blockIdx.y) {
        case 0:  s = s0; d = d0; break;
        case 1:  s = s1; d = d1; break;
        case 2:  s = s2; d = d2; break;
        default: s = s3; d = d3; break;
    }
    if (i < n4) {
        float4 v = ((const float4*)s)[i];
        ((uint4*)d)[i] = make_uint4(f2tf(v.x), f2tf(v.y), f2tf(v.z), f2tf(v.w));
    }
}

// ---------------------------------------------------------------------------
// V transpose+convert: g_V [b][s][h*64+d] f32 -> g_VtT [(b*H+h)][d][s] fp16.
// One 64x64 tile per block (256 thr) through padded SMEM.
// ---------------------------------------------------------------------------
__global__ void cvt_vt(const float* __restrict__ V, __half* __restrict__ Vt) {
    __shared__ float st[64][68];
    const int t = threadIdx.x;
    const int kt = blockIdx.x, h = blockIdx.y, b = blockIdx.z;
    const float* src = V + ((size_t)b * SEQ + (size_t)kt * 64) * D_MODEL + h * DK;
    const int kv = t >> 2, d0 = (t & 3) * 16;
#pragma unroll
    for (int i = 0; i < 4; i++) {
        float4 v = *(const float4*)(src + (size_t)kv * D_MODEL + d0 + i * 4);
        st[kv][d0 + i * 4 + 0] = v.x;
        st[kv][d0 + i * 4 + 1] = v.y;
        st[kv][d0 + i * 4 + 2] = v.z;
        st[kv][d0 + i * 4 + 3] = v.w;
    }
    __syncthreads();
    const int d = t >> 2, kv0 = (t & 3) * 16;
    __half2* dst = (__half2*)(Vt + (((size_t)(b * NHEADS + h) * DK + d) * SEQ + (size_t)kt * 64 + kv0));
#pragma unroll
    for (int i = 0; i < 8; i++)
        dst[i] = __floats2half2_rn(st[kv0 + 2 * i][d], st[kv0 + 2 * i + 1][d]);
}

// ---------------------------------------------------------------------------
// TF32 GEMM core (NT), inputs pre-rounded tf32. BM=BN=128, BK=32, cp.async x2.
// (unchanged)
// ---------------------------------------------------------------------------
#define BM 128
#define BN 128
#define GNKT (D_MODEL / 32)   // 32

__device__ __forceinline__ void gemm_body(
    const float* __restrict__ A, const float* __restrict__ B,
    const float* __restrict__ bias, float* __restrict__ C,
    float scale, int outcvt, int m0, int n0, uint32_t* gsm)
{
    const uint32_t smemb = smem_u32(gsm);
    const int t = threadIdx.x, l = t & 31, w = t >> 5;
    const int wm = w & 1, wn = w >> 1;
    const int r = l >> 2, c = l & 3;

    uint32_t adst[4], bdst[4];
    const float *asrc[4], *bsrc[4];
#pragma unroll
    for (int i = 0; i < 4; i++) {
        const int ch = t + i * 256, rr = ch >> 3, g = ch & 7;
        const uint32_t d = (uint32_t)(rr * 32 + ((g ^ (rr & 7)) << 2)) * 4;
        adst[i] = d;
        bdst[i] = d + 16384;
        asrc[i] = A + (size_t)(m0 + rr) * D_MODEL + g * 4;
        bsrc[i] = B + (size_t)(n0 + rr) * D_MODEL + g * 4;
    }

    float acc[4][4][4];
#pragma unroll
    for (int mt = 0; mt < 4; mt++)
#pragma unroll
        for (int nt = 0; nt < 4; nt++)
#pragma unroll
            for (int q = 0; q < 4; q++) acc[mt][nt][q] = 0.f;

#pragma unroll
    for (int i = 0; i < 4; i++) { cp16(smemb + adst[i], asrc[i]); cp16(smemb + bdst[i], bsrc[i]); }
    CP_COMMIT;

    for (int kt = 0; kt < GNKT; kt++) {
        const int buf = kt & 1;
        if (kt + 1 < GNKT) {
            const int ko = (kt + 1) * 32;
            const uint32_t bo = (uint32_t)(buf ^ 1) * 32768u;
#pragma unroll
            for (int i = 0; i < 4; i++) {
                cp16(smemb + bo + adst[i], asrc[i] + ko);
                cp16(smemb + bo + bdst[i], bsrc[i] + ko);
            }
            CP_COMMIT;
            CP_WAIT1;
        } else {
            CP_WAIT0;
        }
        __syncthreads();

        const uint32_t* sa = gsm + buf * 8192;
        const uint32_t* sb = sa + 4096;
#pragma unroll
        for (int kk = 0; kk < 4; kk++) {
            const int g0 = 2 * kk, g1 = 2 * kk + 1;
            const int o0 = ((g0 ^ r) << 2) + c;
            const int o1 = ((g1 ^ r) << 2) + c;
            uint32_t af[4][4], bf[4][2];
#pragma unroll
            for (int mt = 0; mt < 4; mt++) {
                const int ra = (wm * 64 + mt * 16 + r) * 32;
                af[mt][0] = sa[ra + o0];
                af[mt][1] = sa[ra + 256 + o0];
                af[mt][2] = sa[ra + o1];
                af[mt][3] = sa[ra + 256 + o1];
            }
#pragma unroll
            for (int nt = 0; nt < 4; nt++) {
                const int rb = (wn * 32 + nt * 8 + r) * 32;
                bf[nt][0] = sb[rb + o0];
                bf[nt][1] = sb[rb + o1];
            }
#pragma unroll
            for (int mt = 0; mt < 4; mt++)
#pragma unroll
                for (int nt = 0; nt < 4; nt++)
                    mma_tf32(acc[mt][nt], af[mt], bf[nt]);
        }
        __syncthreads();
    }

    const int cc = c * 2;
#pragma unroll
    for (int mt = 0; mt < 4; mt++) {
        const int row0 = m0 + wm * 64 + mt * 16 + r;
#pragma unroll
        for (int nt = 0; nt < 4; nt++) {
            const int col = n0 + wn * 32 + nt * 8 + cc;
            float bx = 0.f, by = 0.f;
            if (bias) { bx = bias[col]; by = bias[col + 1]; }
            float v0 = acc[mt][nt][0] * scale + bx;
            float v1 = acc[mt][nt][1] * scale + by;
            float v2 = acc[mt][nt][2] * scale + bx;
            float v3 = acc[mt][nt][3] * scale + by;
            if (outcvt) { v0 = tfr(v0); v1 = tfr(v1); v2 = tfr(v2); v3 = tfr(v3); }
            *(float2*)(C + (size_t)row0 * D_MODEL + col) = make_float2(v0, v1);
            *(float2*)(C + (size_t)(row0 + 8) * D_MODEL + col) = make_float2(v2, v3);
        }
    }
}

// Fused QKV projection
__global__ __launch_bounds__(256, 2) void gemm_qkv(
    const float* __restrict__ X,
    const float* __restrict__ Wq, const float* __restrict__ Wk, const float* __restrict__ Wv,
    float* __restrict__ Qo, float* __restrict__ Ko, float* __restrict__ Vo)
{
    extern __shared__ uint32_t gsm[];
    const int seg = blockIdx.x >> 3;
    const int n0  = (blockIdx.x & 7) * BN;
    const int m0  = blockIdx.y * BM;
    const float* B = (seg == 0) ? Wq : (seg == 1) ? Wk : Wv;
    float* C       = (seg == 0) ? Qo : (seg == 1) ? Ko : Vo;
    const float sc = (seg == 0) ? 0.125f : 1.0f;
    gemm_body(X, B, nullptr, C, sc, 1, m0, n0, gsm);
}

__global__ __launch_bounds__(256, 2) void gemm_out(
    const float* __restrict__ A, const float* __restrict__ B,
    const float* __restrict__ bias, float* __restrict__ C)
{
    extern __shared__ uint32_t gsm[];
    gemm_body(A, B, bias, C, 1.0f, 0, blockIdx.y * BM, blockIdx.x * BN, gsm);
}

// ---------------------------------------------------------------------------
// Flash attention: S in tf32 (Q/K as before), PV in fp16 m16n8k16.
// The S D-fragment IS the fp16 A-fragment -> softmax permute = 4 cvt, 0 shfl.
// V pre-transposed fp16 [d][kv] in GMEM, cp.async'd, conflict-free LDS.32.
// 128 threads = 4 fat warps x 32 q-rows, BQ=128, double-buffered K+Vt.
// ---------------------------------------------------------------------------
#define FBQ 128
#define FTH 128
#define FNT (SEQ / 64)   // 32
// SMEM words: K [0,8192) (2 bufs x 4096); Vt [8192,12288) (2 bufs x 2048)
#define FSMB (12288 * 4)

__global__ void __launch_bounds__(FTH, 2) flash_tc(
    const float* __restrict__ Q,
    const float* __restrict__ K,
    const __half* __restrict__ Vt,
    float* __restrict__ O)
{
    extern __shared__ uint32_t fsm[];
    const uint32_t smemb = smem_u32(fsm);
    const int t = threadIdx.x, l = t & 31, w = t >> 5;   // w: 0..3
    const int r = l >> 2, c = l & 3;
    const int q0 = blockIdx.x * FBQ;
    const size_t base  = (size_t)blockIdx.z * SEQ * D_MODEL + (size_t)blockIdx.y * DK;
    const size_t baseV = (size_t)(blockIdx.z * NHEADS + blockIdx.y) * DK * SEQ;

    // Q A-fragments: 32 q-rows per warp (pre-rounded tf32, scale folded)
    uint32_t qa[2][8][4];
#pragma unroll
    for (int mi = 0; mi < 2; mi++) {
        const float* qp0 = Q + base + (size_t)(q0 + w * 32 + mi * 16 + r) * D_MODEL;
        const float* qp1 = qp0 + 8 * D_MODEL;
#pragma unroll
        for (int kk = 0; kk < 8; kk++) {
            qa[mi][kk][0] = __float_as_uint(qp0[kk * 8 + c]);
            qa[mi][kk][1] = __float_as_uint(qp1[kk * 8 + c]);
            qa[mi][kk][2] = __float_as_uint(qp0[kk * 8 + c + 4]);
            qa[mi][kk][3] = __float_as_uint(qp1[kk * 8 + c + 4]);
        }
    }

    float o[2][8][4];
#pragma unroll
    for (int mi = 0; mi < 2; mi++)
#pragma unroll
        for (int j = 0; j < 8; j++)
#pragma unroll
            for (int q = 0; q < 4; q++) o[mi][j][q] = 0.f;
    float lsA[2] = {0.f, 0.f};
    float lsB[2] = {0.f, 0.f};

    // K loader (round-11 proven): rows r0+8i, granule gq, perm3 key
    const int gq = t & 15;
    const int r0 = t >> 4;
    const int sgk = (gq & 8) | ((gq ^ perm3(r0)) & 7);
    const uint32_t kd0 = (uint32_t)(r0 * 64 + sgk * 4) * 4;
    const float* kbase = K + base + (size_t)r0 * D_MODEL + gq * 4;

    // Vt loader: 4 granule-chunks per thread, key = d&7
    uint32_t vdst[4];
    const __half* vsrc[4];
#pragma unroll
    for (int i = 0; i < 4; i++) {
        const int idx = t + i * FTH, d = idx >> 3, g = idx & 7;
        vdst[i] = (uint32_t)(8192 + d * 32 + ((g ^ (d & 7)) << 2)) * 4;
        vsrc[i] = Vt + baseV + (size_t)d * SEQ + g * 8;
    }

    // preload kt = 0
#pragma unroll
    for (int i = 0; i < 8; i++)
        cp16(smemb + kd0 + i * 2048u, kbase + (size_t)i * 8 * D_MODEL);
#pragma unroll
    for (int i = 0; i < 4; i++) cp16(smemb + vdst[i], vsrc[i]);
    CP_COMMIT;

    const int pk = perm3(r);

    for (int kt = 0; kt < FNT; kt++) {
        const int buf = kt & 1;
        if (kt + 1 < FNT) {
            const size_t goK = (size_t)(kt + 1) * 64 * D_MODEL;
            const int goV = (kt + 1) * 64;
            const uint32_t boK = (uint32_t)(buf ^ 1) * 16384u;
            const uint32_t boV = (uint32_t)(buf ^ 1) * 8192u;
#pragma unroll
            for (int i = 0; i < 8; i++)
                cp16(smemb + boK + kd0 + i * 2048u, kbase + goK + (size_t)i * 8 * D_MODEL);
#pragma unroll
            for (int i = 0; i < 4; i++) cp16(smemb + boV + vdst[i], vsrc[i] + goV);
            CP_COMMIT;
            CP_WAIT1;
        } else {
            CP_WAIT0;
        }
        __syncthreads();

        const uint32_t* sk = fsm + buf * 4096;
        const uint32_t* sv = fsm + 8192 + buf * 2048;

        // ---- S = Q K^T (tf32) ----
        float s[2][8][4];
#pragma unroll
        for (int mi = 0; mi < 2; mi++)
#pragma unroll
            for (int j = 0; j < 8; j++)
#pragma unroll
                for (int q = 0; q < 4; q++) s[mi][j][q] = 0.f;

#pragma unroll
        for (int kk = 0; kk < 8; kk++) {
            const int g0 = 2 * kk, g1 = 2 * kk + 1;
            const int ok0 = ((g0 & 8) | ((g0 ^ pk) & 7)) * 4 + c;
            const int ok1 = ((g1 & 8) | ((g1 ^ pk) & 7)) * 4 + c;
#pragma unroll
            for (int j = 0; j < 8; j++) {
                const int row = (j * 8 + r) * 64;
                uint32_t bf[2];
                bf[0] = sk[row + ok0];
                bf[1] = sk[row + ok1];
                mma_tf32(s[0][j], qa[0][kk], bf);
                mma_tf32(s[1][j], qa[1][kk], bf);
            }
        }

        // ---- exp -> fp16 pack (no shuffles) -> PV (fp16 k16) ----
#pragma unroll
        for (int u = 0; u < 4; u++) {
            uint32_t pa[2][4];
#pragma unroll
            for (int mi = 0; mi < 2; mi++) {
                const float e0 = expc(s[mi][2 * u][0]);
                const float e1 = expc(s[mi][2 * u][1]);
                const float e2 = expc(s[mi][2 * u][2]);
                const float e3 = expc(s[mi][2 * u][3]);
                const float f0 = expc(s[mi][2 * u + 1][0]);
                const float f1 = expc(s[mi][2 * u + 1][1]);
                const float f2 = expc(s[mi][2 * u + 1][2]);
                const float f3 = expc(s[mi][2 * u + 1][3]);
                lsA[mi] += (e0 + e1) + (f0 + f1);
                lsB[mi] += (e2 + e3) + (f2 + f3);
                pa[mi][0] = h2pack(e0, e1);
                pa[mi][1] = h2pack(e2, e3);
                pa[mi][2] = h2pack(f0, f1);
                pa[mi][3] = h2pack(f2, f3);
            }
            const int gv0 = 2 * u, gv1 = 2 * u + 1;
#pragma unroll
            for (int j = 0; j < 8; j++) {
                const int row = (j * 8 + r) * 32;
                const uint32_t b0 = sv[row + ((gv0 ^ r) << 2) + c];
                const uint32_t b1 = sv[row + ((gv1 ^ r) << 2) + c];
                mma_f16(o[0][j], pa[0], b0, b1);
                mma_f16(o[1][j], pa[1], b0, b1);
            }
        }
        __syncthreads();
    }

    // ---- one-time l reduction, normalize + store (tf32-rounded) ----
#pragma unroll
    for (int mi = 0; mi < 2; mi++) {
#pragma unroll
        for (int off = 1; off <= 2; off <<= 1) {
            lsA[mi] += __shfl_xor_sync(0xffffffffu, lsA[mi], off);
            lsB[mi] += __shfl_xor_sync(0xffffffffu, lsB[mi], off);
        }
    }
#pragma unroll
    for (int mi = 0; mi < 2; mi++) {
        const float i0 = 1.0f / lsA[mi];
        const float i1 = 1.0f / lsB[mi];
        float* r0p = O + base + (size_t)(q0 + w * 32 + mi * 16 + r) * D_MODEL;
        float* r1p = r0p + 8 * D_MODEL;
#pragma unroll
        for (int j = 0; j < 8; j++) {
            const int col = j * 8 + c * 2;
            *(float2*)(r0p + col) = make_float2(tfr(o[mi][j][0] * i0), tfr(o[mi][j][1] * i0));
            *(float2*)(r1p + col) = make_float2(tfr(o[mi][j][2] * i1), tfr(o[mi][j][3] * i1));
        }
    }
}

// ---------------------------------------------------------------------------
extern "C" void kernel_launch(void* const* d_in, const int* in_sizes, int n_in,
                              void* d_out, int out_size)
{
    const float* X   = (const float*)d_in[0];
    const float* W_q = (const float*)d_in[1];
    const float* W_k = (const float*)d_in[2];
    const float* W_v = (const float*)d_in[3];
    const float* W_h = (const float*)d_in[4];
    const float* b_h = (const float*)d_in[5];
    float* out = (float*)d_out;

    float *Qp, *Kp, *Vp, *Hp, *Xt, *Wq, *Wk, *Wv, *Wh;
    __half* Vth;
    cudaGetSymbolAddress((void**)&Qp, g_Q);
    cudaGetSymbolAddress((void**)&Kp, g_K);
    cudaGetSymbolAddress((void**)&Vp, g_V);
    cudaGetSymbolAddress((void**)&Hp, g_H);
    cudaGetSymbolAddress((void**)&Xt, g_Xt);
    cudaGetSymbolAddress((void**)&Wq, g_Wqt);
    cudaGetSymbolAddress((void**)&Wk, g_Wkt);
    cudaGetSymbolAddress((void**)&Wv, g_Wvt);
    cudaGetSymbolAddress((void**)&Wh, g_Wht);
    cudaGetSymbolAddress((void**)&Vth, g_VtT);

    const int GSM = 65536;
    cudaFuncSetAttribute(gemm_qkv, cudaFuncAttributeMaxDynamicSharedMemorySize, GSM);
    cudaFuncSetAttribute(gemm_out, cudaFuncAttributeMaxDynamicSharedMemorySize, GSM);
    cudaFuncSetAttribute(flash_tc, cudaFuncAttributeMaxDynamicSharedMemorySize, FSMB);

    const int nX4 = MROWS * D_MODEL / 4;
    const int nW4 = D_MODEL * D_MODEL / 4;
    cvt_tf32<<<nX4 / 256, 256>>>(Xt, X, nX4);
    dim3 gw(nW4 / 256, 4);
    cvt_w4<<<gw, 256>>>(Wq, W_q, Wk, W_k, Wv, W_v, Wh, W_h, nW4);

    dim3 gq(24, MROWS / BM);             // fused QKV
    gemm_qkv<<<gq, 256, GSM>>>(Xt, Wq, Wk, Wv, Qp, Kp, Vp);

    dim3 gv(SEQ / 64, NHEADS, BATCH);    // V transpose+fp16
    cvt_vt<<<gv, 256>>>(Vp, Vth);

    dim3 gridF(SEQ / FBQ, NHEADS, BATCH);   // (16, 16, 4) = 1024 CTAs
    flash_tc<<<gridF, FTH, FSMB>>>(Qp, Kp, Vth, Hp);

    dim3 gg(D_MODEL / BN, MROWS / BM);
    gemm_out<<<gg, 256, GSM>>>(Hp, Wh, b_h, out);
}

// round 13
// speedup vs baseline: 1.9022x; 1.1223x over previous
#include <cuda_runtime.h>
#include <cuda_fp16.h>
#include <cstdint>
#include <math.h>

#define D_MODEL 1024
#define NHEADS  16
#define DK      64
#define BATCH   4
#define SEQ     2048
#define MROWS   (BATCH * SEQ)   // 8192

// Scratch (allocation-free rule: __device__ globals)
__device__ float  g_V[MROWS * D_MODEL];
__device__ float  g_H[MROWS * D_MODEL];
__device__ float  g_Xt[MROWS * D_MODEL];
__device__ float  g_Wqt[D_MODEL * D_MODEL];
__device__ float  g_Wkt[D_MODEL * D_MODEL];
__device__ float  g_Wvt[D_MODEL * D_MODEL];
__device__ float  g_Wht[D_MODEL * D_MODEL];
__device__ __half g_Q16[MROWS * D_MODEL];
__device__ __half g_K16[MROWS * D_MODEL];
__device__ __half g_VtT[BATCH * NHEADS * DK * SEQ];   // V transposed fp16 [bh][d][kv]

__device__ __forceinline__ uint32_t f2tf(float f) {
    uint32_t r;
    asm("cvt.rna.tf32.f32 %0, %1;" : "=r"(r) : "f"(f));
    return r;
}
__device__ __forceinline__ float tfr(float f) { return __uint_as_float(f2tf(f)); }

__device__ __forceinline__ void mma_tf32(float* d, const uint32_t* a, const uint32_t* b) {
    asm volatile(
        "mma.sync.aligned.m16n8k8.row.col.f32.tf32.tf32.f32 "
        "{%0,%1,%2,%3}, {%4,%5,%6,%7}, {%8,%9}, {%0,%1,%2,%3};"
        : "+f"(d[0]), "+f"(d[1]), "+f"(d[2]), "+f"(d[3])
        : "r"(a[0]), "r"(a[1]), "r"(a[2]), "r"(a[3]), "r"(b[0]), "r"(b[1]));
}

// fp16 MMA: D(f32) += A(f16) * B(f16), m16n8k16
__device__ __forceinline__ void mma_f16(float* d, const uint32_t* a, uint32_t b0, uint32_t b1) {
    asm volatile(
        "mma.sync.aligned.m16n8k16.row.col.f32.f16.f16.f32 "
        "{%0,%1,%2,%3}, {%4,%5,%6,%7}, {%8,%9}, {%0,%1,%2,%3};"
        : "+f"(d[0]), "+f"(d[1]), "+f"(d[2]), "+f"(d[3])
        : "r"(a[0]), "r"(a[1]), "r"(a[2]), "r"(a[3]), "r"(b0), "r"(b1));
}

__device__ __forceinline__ uint32_t h2pack(float lo, float hi) {
    uint32_t r;
    asm("cvt.rn.f16x2.f32 %0, %1, %2;" : "=r"(r) : "f"(hi), "f"(lo));
    return r;
}

__device__ __forceinline__ uint32_t smem_u32(const void* p) {
    uint32_t a;
    asm("{ .reg .u64 t; cvta.to.shared.u64 t, %1; cvt.u32.u64 %0, t; }" : "=r"(a) : "l"(p));
    return a;
}
__device__ __forceinline__ void cp16(uint32_t dst, const void* src) {
    asm volatile("cp.async.cg.shared.global [%0], [%1], 16;" :: "r"(dst), "l"(src) : "memory");
}
#define CP_COMMIT asm volatile("cp.async.commit_group;" ::: "memory")
#define CP_WAIT1  asm volatile("cp.async.wait_group 1;" ::: "memory")
#define CP_WAIT0  asm volatile("cp.async.wait_group 0;" ::: "memory")

// Fast 2^t on FMA/ALU pipes (no MUFU). |err| ~2.4e-6 rel.
__device__ __forceinline__ float exp2p(float t) {
    t = fmaxf(t, -126.0f);
    const float MAGIC = 12582912.0f;
    float tm = t + MAGIC;
    float n  = tm - MAGIC;
    float f  = t - n;
    float p  = 1.3333558146428443e-3f;
    p = fmaf(p, f, 9.6181291976036003e-3f);
    p = fmaf(p, f, 5.5504108664821580e-2f);
    p = fmaf(p, f, 2.4022650695910071e-1f);
    p = fmaf(p, f, 6.9314718055994531e-1f);
    p = fmaf(p, f, 1.0f);
    int sc = (__float_as_int(tm) + (127 - 0x4B400000)) << 23;
    return p * __int_as_float(sc);
}
#define L2E 1.4426950408889634f
// exp for fp16-bound P: clamp exponent so e^s < 61k (fp16 max 65504)
__device__ __forceinline__ float expc(float s) { return exp2p(fminf(s * L2E, 15.9f)); }

// ---------------------------------------------------------------------------
// tf32 pre-rounding kernels
// ---------------------------------------------------------------------------
__global__ void cvt_tf32(float* __restrict__ dst, const float* __restrict__ src, int n4) {
    int i = blockIdx.x * blockDim.x + threadIdx.x;
    if (i < n4) {
        float4 v = ((const float4*)src)[i];
        ((uint4*)dst)[i] = make_uint4(f2tf(v.x), f2tf(v.y), f2tf(v.z), f2tf(v.w));
    }
}

__global__ void cvt_w4(float* d0, const float* s0, float* d1, const float* s1,
                       float* d2, const float* s2, float* d3, const float* s3, int n4) {
    int i = blockIdx.x * blockDim.x + threadIdx.x;
    const float* s; float* d;
    switch (blockIdx.y) {
        case 0:  s = s0; d = d0; break;
        case 1:  s = s1; d = d1; break;
        case 2:  s = s2; d = d2; break;
        default: s = s3; d = d3; break;
    }
    if (i < n4) {
        float4 v = ((const float4*)s)[i];
        ((uint4*)d)[i] = make_uint4(f2tf(v.x), f2tf(v.y), f2tf(v.z), f2tf(v.w));
    }
}

// ---------------------------------------------------------------------------
// V transpose+convert: g_V [b][s][h*64+d] f32 -> g_VtT [(b*H+h)][d][s] fp16.
// ---------------------------------------------------------------------------
__global__ void cvt_vt(const float* __restrict__ V, __half* __restrict__ Vt) {
    __shared__ float st[64][68];
    const int t = threadIdx.x;
    const int kt = blockIdx.x, h = blockIdx.y, b = blockIdx.z;
    const float* src = V + ((size_t)b * SEQ + (size_t)kt * 64) * D_MODEL + h * DK;
    const int kv = t >> 2, d0 = (t & 3) * 16;
#pragma unroll
    for (int i = 0; i < 4; i++) {
        float4 v = *(const float4*)(src + (size_t)kv * D_MODEL + d0 + i * 4);
        st[kv][d0 + i * 4 + 0] = v.x;
        st[kv][d0 + i * 4 + 1] = v.y;
        st[kv][d0 + i * 4 + 2] = v.z;
        st[kv][d0 + i * 4 + 3] = v.w;
    }
    __syncthreads();
    const int d = t >> 2, kv0 = (t & 3) * 16;
    __half2* dst = (__half2*)(Vt + (((size_t)(b * NHEADS + h) * DK + d) * SEQ + (size_t)kt * 64 + kv0));
#pragma unroll
    for (int i = 0; i < 8; i++)
        dst[i] = __floats2half2_rn(st[kv0 + 2 * i][d], st[kv0 + 2 * i + 1][d]);
}

// ---------------------------------------------------------------------------
// TF32 GEMM core (NT). Optionally writes fp16 output (Ch != null).
// ---------------------------------------------------------------------------
#define BM 128
#define BN 128
#define GNKT (D_MODEL / 32)   // 32

__device__ __forceinline__ void gemm_body(
    const float* __restrict__ A, const float* __restrict__ B,
    const float* __restrict__ bias, float* __restrict__ C, __half* __restrict__ Ch,
    float scale, int outcvt, int m0, int n0, uint32_t* gsm)
{
    const uint32_t smemb = smem_u32(gsm);
    const int t = threadIdx.x, l = t & 31, w = t >> 5;
    const int wm = w & 1, wn = w >> 1;
    const int r = l >> 2, c = l & 3;

    uint32_t adst[4], bdst[4];
    const float *asrc[4], *bsrc[4];
#pragma unroll
    for (int i = 0; i < 4; i++) {
        const int ch = t + i * 256, rr = ch >> 3, g = ch & 7;
        const uint32_t d = (uint32_t)(rr * 32 + ((g ^ (rr & 7)) << 2)) * 4;
        adst[i] = d;
        bdst[i] = d + 16384;
        asrc[i] = A + (size_t)(m0 + rr) * D_MODEL + g * 4;
        bsrc[i] = B + (size_t)(n0 + rr) * D_MODEL + g * 4;
    }

    float acc[4][4][4];
#pragma unroll
    for (int mt = 0; mt < 4; mt++)
#pragma unroll
        for (int nt = 0; nt < 4; nt++)
#pragma unroll
            for (int q = 0; q < 4; q++) acc[mt][nt][q] = 0.f;

#pragma unroll
    for (int i = 0; i < 4; i++) { cp16(smemb + adst[i], asrc[i]); cp16(smemb + bdst[i], bsrc[i]); }
    CP_COMMIT;

    for (int kt = 0; kt < GNKT; kt++) {
        const int buf = kt & 1;
        if (kt + 1 < GNKT) {
            const int ko = (kt + 1) * 32;
            const uint32_t bo = (uint32_t)(buf ^ 1) * 32768u;
#pragma unroll
            for (int i = 0; i < 4; i++) {
                cp16(smemb + bo + adst[i], asrc[i] + ko);
                cp16(smemb + bo + bdst[i], bsrc[i] + ko);
            }
            CP_COMMIT;
            CP_WAIT1;
        } else {
            CP_WAIT0;
        }
        __syncthreads();

        const uint32_t* sa = gsm + buf * 8192;
        const uint32_t* sb = sa + 4096;
#pragma unroll
        for (int kk = 0; kk < 4; kk++) {
            const int g0 = 2 * kk, g1 = 2 * kk + 1;
            const int o0 = ((g0 ^ r) << 2) + c;
            const int o1 = ((g1 ^ r) << 2) + c;
            uint32_t af[4][4], bf[4][2];
#pragma unroll
            for (int mt = 0; mt < 4; mt++) {
                const int ra = (wm * 64 + mt * 16 + r) * 32;
                af[mt][0] = sa[ra + o0];
                af[mt][1] = sa[ra + 256 + o0];
                af[mt][2] = sa[ra + o1];
                af[mt][3] = sa[ra + 256 + o1];
            }
#pragma unroll
            for (int nt = 0; nt < 4; nt++) {
                const int rb = (wn * 32 + nt * 8 + r) * 32;
                bf[nt][0] = sb[rb + o0];
                bf[nt][1] = sb[rb + o1];
            }
#pragma unroll
            for (int mt = 0; mt < 4; mt++)
#pragma unroll
                for (int nt = 0; nt < 4; nt++)
                    mma_tf32(acc[mt][nt], af[mt], bf[nt]);
        }
        __syncthreads();
    }

    const int cc = c * 2;
#pragma unroll
    for (int mt = 0; mt < 4; mt++) {
        const int row0 = m0 + wm * 64 + mt * 16 + r;
#pragma unroll
        for (int nt = 0; nt < 4; nt++) {
            const int col = n0 + wn * 32 + nt * 8 + cc;
            float bx = 0.f, by = 0.f;
            if (bias) { bx = bias[col]; by = bias[col + 1]; }
            float v0 = acc[mt][nt][0] * scale + bx;
            float v1 = acc[mt][nt][1] * scale + by;
            float v2 = acc[mt][nt][2] * scale + bx;
            float v3 = acc[mt][nt][3] * scale + by;
            if (Ch) {
                *(__half2*)(Ch + (size_t)row0 * D_MODEL + col) = __floats2half2_rn(v0, v1);
                *(__half2*)(Ch + (size_t)(row0 + 8) * D_MODEL + col) = __floats2half2_rn(v2, v3);
            } else {
                if (outcvt) { v0 = tfr(v0); v1 = tfr(v1); v2 = tfr(v2); v3 = tfr(v3); }
                *(float2*)(C + (size_t)row0 * D_MODEL + col) = make_float2(v0, v1);
                *(float2*)(C + (size_t)(row0 + 8) * D_MODEL + col) = make_float2(v2, v3);
            }
        }
    }
}

// Fused QKV projection: Q,K emitted fp16; V f32 (tf32-rounded for cvt_vt).
__global__ __launch_bounds__(256, 2) void gemm_qkv(
    const float* __restrict__ X,
    const float* __restrict__ Wq, const float* __restrict__ Wk, const float* __restrict__ Wv,
    __half* __restrict__ Qo, __half* __restrict__ Ko, float* __restrict__ Vo)
{
    extern __shared__ uint32_t gsm[];
    const int seg = blockIdx.x >> 3;
    const int n0  = (blockIdx.x & 7) * BN;
    const int m0  = blockIdx.y * BM;
    if (seg == 0)      gemm_body(X, Wq, nullptr, nullptr, Qo, 0.125f, 0, m0, n0, gsm);
    else if (seg == 1) gemm_body(X, Wk, nullptr, nullptr, Ko, 1.0f,   0, m0, n0, gsm);
    else               gemm_body(X, Wv, nullptr, Vo, nullptr, 1.0f,   1, m0, n0, gsm);
}

__global__ __launch_bounds__(256, 2) void gemm_out(
    const float* __restrict__ A, const float* __restrict__ B,
    const float* __restrict__ bias, float* __restrict__ C)
{
    extern __shared__ uint32_t gsm[];
    gemm_body(A, B, bias, C, nullptr, 1.0f, 0, blockIdx.y * BM, blockIdx.x * BN, gsm);
}

// ---------------------------------------------------------------------------
// Flash attention, all-fp16 MMA inputs (fp32 accum):
//   S = Q K^T via m16n8k16 (Q fp16 A-frags loaded directly as u32 pairs;
//   K fp16 [kv][d] in SMEM, granule-swizzled, conflict-free).
//   PV via m16n8k16 with Vt fp16 [d][kv] (round-12 proven).
// 128 threads = 4 fat warps x 32 q-rows, BQ=128, double-buffered K+Vt.
// ---------------------------------------------------------------------------
#define FBQ 128
#define FTH 128
#define FNT (SEQ / 64)   // 32
// SMEM words: K [0,4096) (2 bufs x 2048); Vt [4096,8192) (2 bufs x 2048)
#define FSMB (8192 * 4)

__global__ void __launch_bounds__(FTH, 2) flash_tc(
    const __half* __restrict__ Q,
    const __half* __restrict__ K,
    const __half* __restrict__ Vt,
    float* __restrict__ O)
{
    extern __shared__ uint32_t fsm[];
    const uint32_t smemb = smem_u32(fsm);
    const int t = threadIdx.x, l = t & 31, w = t >> 5;   // w: 0..3
    const int r = l >> 2, c = l & 3;
    const int q0 = blockIdx.x * FBQ;
    const size_t base  = (size_t)blockIdx.z * SEQ * D_MODEL + (size_t)blockIdx.y * DK;
    const size_t baseV = (size_t)(blockIdx.z * NHEADS + blockIdx.y) * DK * SEQ;

    // Q A-fragments (fp16, m16n8k16): 32 q-rows per warp, 4 k-chunks, 4 u32 each
    uint32_t qa[2][4][4];
#pragma unroll
    for (int mi = 0; mi < 2; mi++) {
        const uint32_t* qp0 = (const uint32_t*)(Q + base + (size_t)(q0 + w * 32 + mi * 16 + r) * D_MODEL);
        const uint32_t* qp1 = qp0 + 8 * (D_MODEL / 2);
#pragma unroll
        for (int kk = 0; kk < 4; kk++) {
            qa[mi][kk][0] = qp0[kk * 8 + c];
            qa[mi][kk][1] = qp1[kk * 8 + c];
            qa[mi][kk][2] = qp0[kk * 8 + c + 4];
            qa[mi][kk][3] = qp1[kk * 8 + c + 4];
        }
    }

    float o[2][8][4];
#pragma unroll
    for (int mi = 0; mi < 2; mi++)
#pragma unroll
        for (int j = 0; j < 8; j++)
#pragma unroll
            for (int q = 0; q < 4; q++) o[mi][j][q] = 0.f;
    float lsA[2] = {0.f, 0.f};
    float lsB[2] = {0.f, 0.f};

    // K loader: fp16 [kv][d] rows = 32 u32 words, granule swizzle g^(row&7).
    // 64 rows x 8 granules = 512 chunks / 128 thr = 4 per thread.
    uint32_t kdst[4];
    const __half* ksrc[4];
#pragma unroll
    for (int i = 0; i < 4; i++) {
        const int idx = t + i * FTH, row = idx >> 3, g = idx & 7;
        kdst[i] = (uint32_t)(row * 32 + ((g ^ (row & 7)) << 2)) * 4;
        ksrc[i] = K + base + (size_t)row * D_MODEL + g * 8;
    }

    // Vt loader (round-12 proven): key = d&7
    uint32_t vdst[4];
    const __half* vsrc[4];
#pragma unroll
    for (int i = 0; i < 4; i++) {
        const int idx = t + i * FTH, d = idx >> 3, g = idx & 7;
        vdst[i] = (uint32_t)(4096 + d * 32 + ((g ^ (d & 7)) << 2)) * 4;
        vsrc[i] = Vt + baseV + (size_t)d * SEQ + g * 8;
    }

    // preload kt = 0
#pragma unroll
    for (int i = 0; i < 4; i++) { cp16(smemb + kdst[i], ksrc[i]); cp16(smemb + vdst[i], vsrc[i]); }
    CP_COMMIT;

    for (int kt = 0; kt < FNT; kt++) {
        const int buf = kt & 1;
        if (kt + 1 < FNT) {
            const size_t goK = (size_t)(kt + 1) * 64 * D_MODEL;
            const int goV = (kt + 1) * 64;
            const uint32_t bo = (uint32_t)(buf ^ 1) * 8192u;
#pragma unroll
            for (int i = 0; i < 4; i++) {
                cp16(smemb + bo + kdst[i], ksrc[i] + goK);
                cp16(smemb + bo + vdst[i], vsrc[i] + goV);
            }
            CP_COMMIT;
            CP_WAIT1;
        } else {
            CP_WAIT0;
        }
        __syncthreads();

        const uint32_t* sk = fsm + buf * 2048;
        const uint32_t* sv = fsm + 4096 + buf * 2048;

        // ---- S = Q K^T (fp16 k16): kk 0..3, kv-rows j 0..7 ----
        float s[2][8][4];
#pragma unroll
        for (int mi = 0; mi < 2; mi++)
#pragma unroll
            for (int j = 0; j < 8; j++)
#pragma unroll
                for (int q = 0; q < 4; q++) s[mi][j][q] = 0.f;

#pragma unroll
        for (int kk = 0; kk < 4; kk++) {
            const int g0 = 2 * kk, g1 = 2 * kk + 1;
#pragma unroll
            for (int j = 0; j < 8; j++) {
                const int row = (j * 8 + r) * 32;
                const uint32_t b0 = sk[row + (((g0 ^ r) & 7) << 2) + c];
                const uint32_t b1 = sk[row + (((g1 ^ r) & 7) << 2) + c];
                mma_f16(s[0][j], qa[0][kk], b0, b1);
                mma_f16(s[1][j], qa[1][kk], b0, b1);
            }
        }

        // ---- exp -> fp16 pack (no shuffles) -> PV (fp16 k16) ----
#pragma unroll
        for (int u = 0; u < 4; u++) {
            uint32_t pa[2][4];
#pragma unroll
            for (int mi = 0; mi < 2; mi++) {
                const float e0 = expc(s[mi][2 * u][0]);
                const float e1 = expc(s[mi][2 * u][1]);
                const float e2 = expc(s[mi][2 * u][2]);
                const float e3 = expc(s[mi][2 * u][3]);
                const float f0 = expc(s[mi][2 * u + 1][0]);
                const float f1 = expc(s[mi][2 * u + 1][1]);
                const float f2 = expc(s[mi][2 * u + 1][2]);
                const float f3 = expc(s[mi][2 * u + 1][3]);
                lsA[mi] += (e0 + e1) + (f0 + f1);
                lsB[mi] += (e2 + e3) + (f2 + f3);
                pa[mi][0] = h2pack(e0, e1);
                pa[mi][1] = h2pack(e2, e3);
                pa[mi][2] = h2pack(f0, f1);
                pa[mi][3] = h2pack(f2, f3);
            }
            const int gv0 = 2 * u, gv1 = 2 * u + 1;
#pragma unroll
            for (int j = 0; j < 8; j++) {
                const int row = (j * 8 + r) * 32;
                const uint32_t b0 = sv[row + ((gv0 ^ r) << 2) + c];
                const uint32_t b1 = sv[row + ((gv1 ^ r) << 2) + c];
                mma_f16(o[0][j], pa[0], b0, b1);
                mma_f16(o[1][j], pa[1], b0, b1);
            }
        }
        __syncthreads();
    }

    // ---- one-time l reduction, normalize + store (tf32-rounded) ----
#pragma unroll
    for (int mi = 0; mi < 2; mi++) {
#pragma unroll
        for (int off = 1; off <= 2; off <<= 1) {
            lsA[mi] += __shfl_xor_sync(0xffffffffu, lsA[mi], off);
            lsB[mi] += __shfl_xor_sync(0xffffffffu, lsB[mi], off);
        }
    }
#pragma unroll
    for (int mi = 0; mi < 2; mi++) {
        const float i0 = 1.0f / lsA[mi];
        const float i1 = 1.0f / lsB[mi];
        float* r0p = O + base + (size_t)(q0 + w * 32 + mi * 16 + r) * D_MODEL;
        float* r1p = r0p + 8 * D_MODEL;
#pragma unroll
        for (int j = 0; j < 8; j++) {
            const int col = j * 8 + c * 2;
            *(float2*)(r0p + col) = make_float2(tfr(o[mi][j][0] * i0), tfr(o[mi][j][1] * i0));
            *(float2*)(r1p + col) = make_float2(tfr(o[mi][j][2] * i1), tfr(o[mi][j][3] * i1));
        }
    }
}

// ---------------------------------------------------------------------------
extern "C" void kernel_launch(void* const* d_in, const int* in_sizes, int n_in,
                              void* d_out, int out_size)
{
    const float* X   = (const float*)d_in[0];
    const float* W_q = (const float*)d_in[1];
    const float* W_k = (const float*)d_in[2];
    const float* W_v = (const float*)d_in[3];
    const float* W_h = (const float*)d_in[4];
    const float* b_h = (const float*)d_in[5];
    float* out = (float*)d_out;

    float *Vp, *Hp, *Xt, *Wq, *Wk, *Wv, *Wh;
    __half *Qh, *Kh, *Vth;
    cudaGetSymbolAddress((void**)&Vp, g_V);
    cudaGetSymbolAddress((void**)&Hp, g_H);
    cudaGetSymbolAddress((void**)&Xt, g_Xt);
    cudaGetSymbolAddress((void**)&Wq, g_Wqt);
    cudaGetSymbolAddress((void**)&Wk, g_Wkt);
    cudaGetSymbolAddress((void**)&Wv, g_Wvt);
    cudaGetSymbolAddress((void**)&Wh, g_Wht);
    cudaGetSymbolAddress((void**)&Qh, g_Q16);
    cudaGetSymbolAddress((void**)&Kh, g_K16);
    cudaGetSymbolAddress((void**)&Vth, g_VtT);

    const int GSM = 65536;
    cudaFuncSetAttribute(gemm_qkv, cudaFuncAttributeMaxDynamicSharedMemorySize, GSM);
    cudaFuncSetAttribute(gemm_out, cudaFuncAttributeMaxDynamicSharedMemorySize, GSM);
    cudaFuncSetAttribute(flash_tc, cudaFuncAttributeMaxDynamicSharedMemorySize, FSMB);

    const int nX4 = MROWS * D_MODEL / 4;
    const int nW4 = D_MODEL * D_MODEL / 4;
    cvt_tf32<<<nX4 / 256, 256>>>(Xt, X, nX4);
    dim3 gw(nW4 / 256, 4);
    cvt_w4<<<gw, 256>>>(Wq, W_q, Wk, W_k, Wv, W_v, Wh, W_h, nW4);

    dim3 gq(24, MROWS / BM);             // fused QKV (Q,K -> fp16; V -> f32)
    gemm_qkv<<<gq, 256, GSM>>>(Xt, Wq, Wk, Wv, Qh, Kh, Vp);

    dim3 gv(SEQ / 64, NHEADS, BATCH);    // V transpose+fp16
    cvt_vt<<<gv, 256>>>(Vp, Vth);

    dim3 gridF(SEQ / FBQ, NHEADS, BATCH);   // (16, 16, 4) = 1024 CTAs
    flash_tc<<<gridF, FTH, FSMB>>>(Qh, Kh, Vth, Hp);

    dim3 gg(D_MODEL / BN, MROWS / BM);
    gemm_out<<<gg, 256, GSM>>>(Hp, Wh, b_h, out);
}

// round 14
// speedup vs baseline: 2.6109x; 1.3725x over previous
#include <cuda_runtime.h>
#include <cuda_fp16.h>
#include <cstdint>
#include <math.h>

#define D_MODEL 1024
#define NHEADS  16
#define DK      64
#define BATCH   4
#define SEQ     2048
#define MROWS   (BATCH * SEQ)   // 8192

// Scratch (allocation-free rule: __device__ globals)
__device__ __half g_X16[MROWS * D_MODEL];
__device__ __half g_Wq16[D_MODEL * D_MODEL];
__device__ __half g_Wk16[D_MODEL * D_MODEL];
__device__ __half g_Wv16[D_MODEL * D_MODEL];
__device__ __half g_Wh16[D_MODEL * D_MODEL];
__device__ __half g_Q16[MROWS * D_MODEL];
__device__ __half g_K16[MROWS * D_MODEL];
__device__ __half g_V16[MROWS * D_MODEL];
__device__ __half g_H16[MROWS * D_MODEL];
__device__ __half g_VtT[BATCH * NHEADS * DK * SEQ];   // V transposed fp16 [bh][d][kv]

// fp16 MMA: D(f32) += A(f16) * B(f16), m16n8k16
__device__ __forceinline__ void mma_f16(float* d, const uint32_t* a, uint32_t b0, uint32_t b1) {
    asm volatile(
        "mma.sync.aligned.m16n8k16.row.col.f32.f16.f16.f32 "
        "{%0,%1,%2,%3}, {%4,%5,%6,%7}, {%8,%9}, {%0,%1,%2,%3};"
        : "+f"(d[0]), "+f"(d[1]), "+f"(d[2]), "+f"(d[3])
        : "r"(a[0]), "r"(a[1]), "r"(a[2]), "r"(a[3]), "r"(b0), "r"(b1));
}

__device__ __forceinline__ uint32_t h2pack(float lo, float hi) {
    uint32_t r;
    asm("cvt.rn.f16x2.f32 %0, %1, %2;" : "=r"(r) : "f"(hi), "f"(lo));
    return r;
}

__device__ __forceinline__ uint32_t smem_u32(const void* p) {
    uint32_t a;
    asm("{ .reg .u64 t; cvta.to.shared.u64 t, %1; cvt.u32.u64 %0, t; }" : "=r"(a) : "l"(p));
    return a;
}
__device__ __forceinline__ void cp16(uint32_t dst, const void* src) {
    asm volatile("cp.async.cg.shared.global [%0], [%1], 16;" :: "r"(dst), "l"(src) : "memory");
}
#define CP_COMMIT asm volatile("cp.async.commit_group;" ::: "memory")
#define CP_WAIT1  asm volatile("cp.async.wait_group 1;" ::: "memory")
#define CP_WAIT0  asm volatile("cp.async.wait_group 0;" ::: "memory")

// Fast 2^t on FMA/ALU pipes (no MUFU). |err| ~2.4e-6 rel.
__device__ __forceinline__ float exp2p(float t) {
    t = fmaxf(t, -126.0f);
    const float MAGIC = 12582912.0f;
    float tm = t + MAGIC;
    float n  = tm - MAGIC;
    float f  = t - n;
    float p  = 1.3333558146428443e-3f;
    p = fmaf(p, f, 9.6181291976036003e-3f);
    p = fmaf(p, f, 5.5504108664821580e-2f);
    p = fmaf(p, f, 2.4022650695910071e-1f);
    p = fmaf(p, f, 6.9314718055994531e-1f);
    p = fmaf(p, f, 1.0f);
    int sc = (__float_as_int(tm) + (127 - 0x4B400000)) << 23;
    return p * __int_as_float(sc);
}
#define L2E 1.4426950408889634f
// exp for fp16-bound P: clamp exponent so e^s < 61k (fp16 max 65504)
__device__ __forceinline__ float expc(float s) { return exp2p(fminf(s * L2E, 15.9f)); }

// ---------------------------------------------------------------------------
// fp32 -> fp16 conversion kernels
// ---------------------------------------------------------------------------
__global__ void cvt_h(__half* __restrict__ dst, const float* __restrict__ src, int n4) {
    int i = blockIdx.x * blockDim.x + threadIdx.x;
    if (i < n4) {
        float4 v = ((const float4*)src)[i];
        uint2 o;
        o.x = h2pack(v.x, v.y);
        o.y = h2pack(v.z, v.w);
        ((uint2*)dst)[i] = o;
    }
}

__global__ void cvt_h4(__half* d0, const float* s0, __half* d1, const float* s1,
                       __half* d2, const float* s2, __half* d3, const float* s3, int n4) {
    int i = blockIdx.x * blockDim.x + threadIdx.x;
    const float* s; __half* d;
    switch (blockIdx.y) {
        case 0:  s = s0; d = d0; break;
        case 1:  s = s1; d = d1; break;
        case 2:  s = s2; d = d2; break;
        default: s = s3; d = d3; break;
    }
    if (i < n4) {
        float4 v = ((const float4*)s)[i];
        uint2 o;
        o.x = h2pack(v.x, v.y);
        o.y = h2pack(v.z, v.w);
        ((uint2*)d)[i] = o;
    }
}

// ---------------------------------------------------------------------------
// V transpose: g_V16 [b][s][h*64+d] fp16 -> g_VtT [(b*H+h)][d][s] fp16.
// ---------------------------------------------------------------------------
__global__ void cvt_vt(const __half* __restrict__ V, __half* __restrict__ Vt) {
    __shared__ __half st[64][72];
    const int t = threadIdx.x;
    const int kt = blockIdx.x, h = blockIdx.y, b = blockIdx.z;
    const __half* src = V + ((size_t)b * SEQ + (size_t)kt * 64) * D_MODEL + h * DK;
    const int kv = t >> 2, d0 = (t & 3) * 16;
#pragma unroll
    for (int i = 0; i < 2; i++) {
        uint4 v = *(const uint4*)(src + (size_t)kv * D_MODEL + d0 + i * 8);
        *(uint4*)&st[kv][d0 + i * 8] = v;
    }
    __syncthreads();
    const int d = t >> 2, kv0 = (t & 3) * 16;
    __half2* dst = (__half2*)(Vt + (((size_t)(b * NHEADS + h) * DK + d) * SEQ + (size_t)kt * 64 + kv0));
#pragma unroll
    for (int i = 0; i < 8; i++)
        dst[i] = __halves2half2(st[kv0 + 2 * i][d], st[kv0 + 2 * i + 1][d]);
}

// ---------------------------------------------------------------------------
// FP16 GEMM core (NT): C = scale*(A@B^T)+bias. A,B fp16 [rows][1024].
// BM=BN=128, k-tile = 64 halves (128B/row), 16 k-tiles, cp.async x2.
// SMEM rows: 32 u32 words, granule swizzle g^(row&7) (flash-proven).
// ---------------------------------------------------------------------------
#define BM 128
#define BN 128
#define HNKT (D_MODEL / 64)   // 16

__device__ __forceinline__ void gemm_body(
    const __half* __restrict__ A, const __half* __restrict__ B,
    const float* __restrict__ bias, float* __restrict__ C, __half* __restrict__ Ch,
    float scale, int m0, int n0, uint32_t* gsm)
{
    const uint32_t smemb = smem_u32(gsm);
    const int t = threadIdx.x, l = t & 31, w = t >> 5;
    const int wm = w & 1, wn = w >> 1;
    const int r = l >> 2, c = l & 3;

    // loaders: 4 granule-chunks per thread per array (128 rows x 8 granules)
    uint32_t adst[4];
    const __half *asrc[4], *bsrc[4];
#pragma unroll
    for (int i = 0; i < 4; i++) {
        const int idx = t + i * 256, row = idx >> 3, g = idx & 7;
        adst[i] = (uint32_t)(row * 32 + ((g ^ (row & 7)) << 2)) * 4;
        asrc[i] = A + (size_t)(m0 + row) * D_MODEL + g * 8;
        bsrc[i] = B + (size_t)(n0 + row) * D_MODEL + g * 8;
    }

    float acc[4][4][4];
#pragma unroll
    for (int mt = 0; mt < 4; mt++)
#pragma unroll
        for (int nt = 0; nt < 4; nt++)
#pragma unroll
            for (int q = 0; q < 4; q++) acc[mt][nt][q] = 0.f;

#pragma unroll
    for (int i = 0; i < 4; i++) {
        cp16(smemb + adst[i], asrc[i]);
        cp16(smemb + 16384u + adst[i], bsrc[i]);
    }
    CP_COMMIT;

    for (int kt = 0; kt < HNKT; kt++) {
        const int buf = kt & 1;
        if (kt + 1 < HNKT) {
            const int ko = (kt + 1) * 64;
            const uint32_t bo = (uint32_t)(buf ^ 1) * 32768u;
#pragma unroll
            for (int i = 0; i < 4; i++) {
                cp16(smemb + bo + adst[i], asrc[i] + ko);
                cp16(smemb + bo + 16384u + adst[i], bsrc[i] + ko);
            }
            CP_COMMIT;
            CP_WAIT1;
        } else {
            CP_WAIT0;
        }
        __syncthreads();

        const uint32_t* sa = gsm + buf * 8192;
        const uint32_t* sb = sa + 4096;
#pragma unroll
        for (int kk = 0; kk < 4; kk++) {
            const int g0 = 2 * kk, g1 = 2 * kk + 1;
            const int o0 = (((g0 ^ r) & 7) << 2) + c;
            const int o1 = (((g1 ^ r) & 7) << 2) + c;
            uint32_t af[4][4], bf[4][2];
#pragma unroll
            for (int mt = 0; mt < 4; mt++) {
                const int ra = (wm * 64 + mt * 16 + r) * 32;
                af[mt][0] = sa[ra + o0];
                af[mt][1] = sa[ra + 256 + o0];
                af[mt][2] = sa[ra + o1];
                af[mt][3] = sa[ra + 256 + o1];
            }
#pragma unroll
            for (int nt = 0; nt < 4; nt++) {
                const int rb = (wn * 32 + nt * 8 + r) * 32;
                bf[nt][0] = sb[rb + o0];
                bf[nt][1] = sb[rb + o1];
            }
#pragma unroll
            for (int mt = 0; mt < 4; mt++)
#pragma unroll
                for (int nt = 0; nt < 4; nt++)
                    mma_f16(acc[mt][nt], af[mt], bf[nt][0], bf[nt][1]);
        }
        __syncthreads();
    }

    const int cc = c * 2;
#pragma unroll
    for (int mt = 0; mt < 4; mt++) {
        const int row0 = m0 + wm * 64 + mt * 16 + r;
#pragma unroll
        for (int nt = 0; nt < 4; nt++) {
            const int col = n0 + wn * 32 + nt * 8 + cc;
            float bx = 0.f, by = 0.f;
            if (bias) { bx = bias[col]; by = bias[col + 1]; }
            float v0 = acc[mt][nt][0] * scale + bx;
            float v1 = acc[mt][nt][1] * scale + by;
            float v2 = acc[mt][nt][2] * scale + bx;
            float v3 = acc[mt][nt][3] * scale + by;
            if (Ch) {
                *(uint32_t*)(Ch + (size_t)row0 * D_MODEL + col) = h2pack(v0, v1);
                *(uint32_t*)(Ch + (size_t)(row0 + 8) * D_MODEL + col) = h2pack(v2, v3);
            } else {
                *(float2*)(C + (size_t)row0 * D_MODEL + col) = make_float2(v0, v1);
                *(float2*)(C + (size_t)(row0 + 8) * D_MODEL + col) = make_float2(v2, v3);
            }
        }
    }
}

// Fused QKV projection: all outputs fp16.
__global__ __launch_bounds__(256, 2) void gemm_qkv(
    const __half* __restrict__ X,
    const __half* __restrict__ Wq, const __half* __restrict__ Wk, const __half* __restrict__ Wv,
    __half* __restrict__ Qo, __half* __restrict__ Ko, __half* __restrict__ Vo)
{
    extern __shared__ uint32_t gsm[];
    const int seg = blockIdx.x >> 3;
    const int n0  = (blockIdx.x & 7) * BN;
    const int m0  = blockIdx.y * BM;
    if (seg == 0)      gemm_body(X, Wq, nullptr, nullptr, Qo, 0.125f, m0, n0, gsm);
    else if (seg == 1) gemm_body(X, Wk, nullptr, nullptr, Ko, 1.0f,   m0, n0, gsm);
    else               gemm_body(X, Wv, nullptr, nullptr, Vo, 1.0f,   m0, n0, gsm);
}

__global__ __launch_bounds__(256, 2) void gemm_out(
    const __half* __restrict__ A, const __half* __restrict__ B,
    const float* __restrict__ bias, float* __restrict__ C)
{
    extern __shared__ uint32_t gsm[];
    gemm_body(A, B, bias, C, nullptr, 1.0f, blockIdx.y * BM, blockIdx.x * BN, gsm);
}

// ---------------------------------------------------------------------------
// Flash attention, all-fp16 MMA inputs (fp32 accum). Unchanged from round 13
// except the epilogue writes fp16 H (feeds the fp16 output GEMM).
// ---------------------------------------------------------------------------
#define FBQ 128
#define FTH 128
#define FNT (SEQ / 64)   // 32
#define FSMB (8192 * 4)

__global__ void __launch_bounds__(FTH, 2) flash_tc(
    const __half* __restrict__ Q,
    const __half* __restrict__ K,
    const __half* __restrict__ Vt,
    __half* __restrict__ O)
{
    extern __shared__ uint32_t fsm[];
    const uint32_t smemb = smem_u32(fsm);
    const int t = threadIdx.x, l = t & 31, w = t >> 5;   // w: 0..3
    const int r = l >> 2, c = l & 3;
    const int q0 = blockIdx.x * FBQ;
    const size_t base  = (size_t)blockIdx.z * SEQ * D_MODEL + (size_t)blockIdx.y * DK;
    const size_t baseV = (size_t)(blockIdx.z * NHEADS + blockIdx.y) * DK * SEQ;

    // Q A-fragments (fp16 k16): 32 q-rows per warp, 4 k-chunks
    uint32_t qa[2][4][4];
#pragma unroll
    for (int mi = 0; mi < 2; mi++) {
        const uint32_t* qp0 = (const uint32_t*)(Q + base + (size_t)(q0 + w * 32 + mi * 16 + r) * D_MODEL);
        const uint32_t* qp1 = qp0 + 8 * (D_MODEL / 2);
#pragma unroll
        for (int kk = 0; kk < 4; kk++) {
            qa[mi][kk][0] = qp0[kk * 8 + c];
            qa[mi][kk][1] = qp1[kk * 8 + c];
            qa[mi][kk][2] = qp0[kk * 8 + c + 4];
            qa[mi][kk][3] = qp1[kk * 8 + c + 4];
        }
    }

    float o[2][8][4];
#pragma unroll
    for (int mi = 0; mi < 2; mi++)
#pragma unroll
        for (int j = 0; j < 8; j++)
#pragma unroll
            for (int q = 0; q < 4; q++) o[mi][j][q] = 0.f;
    float lsA[2] = {0.f, 0.f};
    float lsB[2] = {0.f, 0.f};

    // K loader: fp16 [kv][d] rows = 32 u32 words, granule swizzle g^(row&7)
    uint32_t kdst[4];
    const __half* ksrc[4];
#pragma unroll
    for (int i = 0; i < 4; i++) {
        const int idx = t + i * FTH, row = idx >> 3, g = idx & 7;
        kdst[i] = (uint32_t)(row * 32 + ((g ^ (row & 7)) << 2)) * 4;
        ksrc[i] = K + base + (size_t)row * D_MODEL + g * 8;
    }
    // Vt loader: key = d&7
    uint32_t vdst[4];
    const __half* vsrc[4];
#pragma unroll
    for (int i = 0; i < 4; i++) {
        const int idx = t + i * FTH, d = idx >> 3, g = idx & 7;
        vdst[i] = (uint32_t)(4096 + d * 32 + ((g ^ (d & 7)) << 2)) * 4;
        vsrc[i] = Vt + baseV + (size_t)d * SEQ + g * 8;
    }

    // preload kt = 0
#pragma unroll
    for (int i = 0; i < 4; i++) { cp16(smemb + kdst[i], ksrc[i]); cp16(smemb + vdst[i], vsrc[i]); }
    CP_COMMIT;

    for (int kt = 0; kt < FNT; kt++) {
        const int buf = kt & 1;
        if (kt + 1 < FNT) {
            const size_t goK = (size_t)(kt + 1) * 64 * D_MODEL;
            const int goV = (kt + 1) * 64;
            const uint32_t bo = (uint32_t)(buf ^ 1) * 8192u;
#pragma unroll
            for (int i = 0; i < 4; i++) {
                cp16(smemb + bo + kdst[i], ksrc[i] + goK);
                cp16(smemb + bo + vdst[i], vsrc[i] + goV);
            }
            CP_COMMIT;
            CP_WAIT1;
        } else {
            CP_WAIT0;
        }
        __syncthreads();

        const uint32_t* sk = fsm + buf * 2048;
        const uint32_t* sv = fsm + 4096 + buf * 2048;

        // ---- S = Q K^T (fp16 k16) ----
        float s[2][8][4];
#pragma unroll
        for (int mi = 0; mi < 2; mi++)
#pragma unroll
            for (int j = 0; j < 8; j++)
#pragma unroll
                for (int q = 0; q < 4; q++) s[mi][j][q] = 0.f;

#pragma unroll
        for (int kk = 0; kk < 4; kk++) {
            const int g0 = 2 * kk, g1 = 2 * kk + 1;
#pragma unroll
            for (int j = 0; j < 8; j++) {
                const int row = (j * 8 + r) * 32;
                const uint32_t b0 = sk[row + (((g0 ^ r) & 7) << 2) + c];
                const uint32_t b1 = sk[row + (((g1 ^ r) & 7) << 2) + c];
                mma_f16(s[0][j], qa[0][kk], b0, b1);
                mma_f16(s[1][j], qa[1][kk], b0, b1);
            }
        }

        // ---- exp -> fp16 pack (no shuffles) -> PV (fp16 k16) ----
#pragma unroll
        for (int u = 0; u < 4; u++) {
            uint32_t pa[2][4];
#pragma unroll
            for (int mi = 0; mi < 2; mi++) {
                const float e0 = expc(s[mi][2 * u][0]);
                const float e1 = expc(s[mi][2 * u][1]);
                const float e2 = expc(s[mi][2 * u][2]);
                const float e3 = expc(s[mi][2 * u][3]);
                const float f0 = expc(s[mi][2 * u + 1][0]);
                const float f1 = expc(s[mi][2 * u + 1][1]);
                const float f2 = expc(s[mi][2 * u + 1][2]);
                const float f3 = expc(s[mi][2 * u + 1][3]);
                lsA[mi] += (e0 + e1) + (f0 + f1);
                lsB[mi] += (e2 + e3) + (f2 + f3);
                pa[mi][0] = h2pack(e0, e1);
                pa[mi][1] = h2pack(e2, e3);
                pa[mi][2] = h2pack(f0, f1);
                pa[mi][3] = h2pack(f2, f3);
            }
            const int gv0 = 2 * u, gv1 = 2 * u + 1;
#pragma unroll
            for (int j = 0; j < 8; j++) {
                const int row = (j * 8 + r) * 32;
                const uint32_t b0 = sv[row + ((gv0 ^ r) << 2) + c];
                const uint32_t b1 = sv[row + ((gv1 ^ r) << 2) + c];
                mma_f16(o[0][j], pa[0], b0, b1);
                mma_f16(o[1][j], pa[1], b0, b1);
            }
        }
        __syncthreads();
    }

    // ---- one-time l reduction, normalize + store fp16 ----
#pragma unroll
    for (int mi = 0; mi < 2; mi++) {
#pragma unroll
        for (int off = 1; off <= 2; off <<= 1) {
            lsA[mi] += __shfl_xor_sync(0xffffffffu, lsA[mi], off);
            lsB[mi] += __shfl_xor_sync(0xffffffffu, lsB[mi], off);
        }
    }
#pragma unroll
    for (int mi = 0; mi < 2; mi++) {
        const float i0 = 1.0f / lsA[mi];
        const float i1 = 1.0f / lsB[mi];
        __half* r0p = O + base + (size_t)(q0 + w * 32 + mi * 16 + r) * D_MODEL;
        __half* r1p = r0p + 8 * D_MODEL;
#pragma unroll
        for (int j = 0; j < 8; j++) {
            const int col = j * 8 + c * 2;
            *(uint32_t*)(r0p + col) = h2pack(o[mi][j][0] * i0, o[mi][j][1] * i0);
            *(uint32_t*)(r1p + col) = h2pack(o[mi][j][2] * i1, o[mi][j][3] * i1);
        }
    }
}

// ---------------------------------------------------------------------------
extern "C" void kernel_launch(void* const* d_in, const int* in_sizes, int n_in,
                              void* d_out, int out_size)
{
    const float* X   = (const float*)d_in[0];
    const float* W_q = (const float*)d_in[1];
    const float* W_k = (const float*)d_in[2];
    const float* W_v = (const float*)d_in[3];
    const float* W_h = (const float*)d_in[4];
    const float* b_h = (const float*)d_in[5];
    float* out = (float*)d_out;

    __half *Xh, *Wq, *Wk, *Wv, *Wh, *Qh, *Kh, *Vh, *Hh, *Vth;
    cudaGetSymbolAddress((void**)&Xh, g_X16);
    cudaGetSymbolAddress((void**)&Wq, g_Wq16);
    cudaGetSymbolAddress((void**)&Wk, g_Wk16);
    cudaGetSymbolAddress((void**)&Wv, g_Wv16);
    cudaGetSymbolAddress((void**)&Wh, g_Wh16);
    cudaGetSymbolAddress((void**)&Qh, g_Q16);
    cudaGetSymbolAddress((void**)&Kh, g_K16);
    cudaGetSymbolAddress((void**)&Vh, g_V16);
    cudaGetSymbolAddress((void**)&Hh, g_H16);
    cudaGetSymbolAddress((void**)&Vth, g_VtT);

    const int GSM = 65536;
    cudaFuncSetAttribute(gemm_qkv, cudaFuncAttributeMaxDynamicSharedMemorySize, GSM);
    cudaFuncSetAttribute(gemm_out, cudaFuncAttributeMaxDynamicSharedMemorySize, GSM);
    cudaFuncSetAttribute(flash_tc, cudaFuncAttributeMaxDynamicSharedMemorySize, FSMB);

    const int nX4 = MROWS * D_MODEL / 4;
    const int nW4 = D_MODEL * D_MODEL / 4;
    cvt_h<<<nX4 / 256, 256>>>(Xh, X, nX4);
    dim3 gw(nW4 / 256, 4);
    cvt_h4<<<gw, 256>>>(Wq, W_q, Wk, W_k, Wv, W_v, Wh, W_h, nW4);

    dim3 gq(24, MROWS / BM);             // fused QKV (fp16 in/out)
    gemm_qkv<<<gq, 256, GSM>>>(Xh, Wq, Wk, Wv, Qh, Kh, Vh);

    dim3 gv(SEQ / 64, NHEADS, BATCH);    // V transpose
    cvt_vt<<<gv, 256>>>(Vh, Vth);

    dim3 gridF(SEQ / FBQ, NHEADS, BATCH);   // (16, 16, 4) = 1024 CTAs
    flash_tc<<<gridF, FTH, FSMB>>>(Qh, Kh, Vth, Hh);

    dim3 gg(D_MODEL / BN, MROWS / BM);
    gemm_out<<<gg, 256, GSM>>>(Hh, Wh, b_h, out);
}